// round 1
// baseline (speedup 1.0000x reference)
#include <cuda_runtime.h>
#include <cstddef>

// Problem constants
#define B_ 8
#define T_ 2048
#define C_ 1024
#define BT_ (B_ * T_)        // 16384
#define C3_ (3 * C_)         // 3072
#define C4_ (4 * C_)         // 4096

// ---------------- scratch (static device globals; no allocation) ----------------
__device__ float g_xn[(size_t)BT_ * C_];    // xn1, later xn2
__device__ float g_y[(size_t)BT_ * C_];     // wkv y, later vv
__device__ float g_x1[(size_t)BT_ * C_];    // x after time mixing
__device__ float g_kvr[(size_t)BT_ * C3_];  // kvr (k,v,r mixed in place)
__device__ float g_h[(size_t)BT_ * C4_];    // channel-mix hidden

// ---------------- LayerNorm ----------------
__global__ void ln_kernel(const float* __restrict__ x,
                          const float* __restrict__ g,
                          const float* __restrict__ b,
                          float* __restrict__ out) {
    size_t row = blockIdx.x;
    int tid = threadIdx.x;  // 256 threads, 4 floats each
    const float4* xr = reinterpret_cast<const float4*>(x + row * C_);
    float4 v = xr[tid];
    float s = v.x + v.y + v.z + v.w;
    float s2 = v.x * v.x + v.y * v.y + v.z * v.z + v.w * v.w;

    // block reduce (sum, sumsq)
    __shared__ float sa[8], sb[8];
    for (int o = 16; o > 0; o >>= 1) {
        s  += __shfl_down_sync(0xffffffffu, s, o);
        s2 += __shfl_down_sync(0xffffffffu, s2, o);
    }
    int w = tid >> 5, l = tid & 31;
    if (l == 0) { sa[w] = s; sb[w] = s2; }
    __syncthreads();
    if (w == 0) {
        s  = (l < 8) ? sa[l] : 0.f;
        s2 = (l < 8) ? sb[l] : 0.f;
        for (int o = 4; o > 0; o >>= 1) {
            s  += __shfl_down_sync(0xffffffffu, s, o);
            s2 += __shfl_down_sync(0xffffffffu, s2, o);
        }
        if (l == 0) { sa[0] = s; sb[0] = s2; }
    }
    __syncthreads();
    float mean = sa[0] * (1.0f / C_);
    float var = sb[0] * (1.0f / C_) - mean * mean;
    float rstd = rsqrtf(var + 1e-5f);

    float4 gg = reinterpret_cast<const float4*>(g)[tid];
    float4 bb = reinterpret_cast<const float4*>(b)[tid];
    float4 o;
    o.x = (v.x - mean) * rstd * gg.x + bb.x;
    o.y = (v.y - mean) * rstd * gg.y + bb.y;
    o.z = (v.z - mean) * rstd * gg.z + bb.z;
    o.w = (v.w - mean) * rstd * gg.w + bb.w;
    reinterpret_cast<float4*>(out + row * C_)[tid] = o;
}

// ---------------- SGEMM: C[M,N] = A[M,K] @ B[K,N] (row-major, fp32) ----------------
// 64x64 tile, BK=16, 256 threads, 4x4 per-thread micro-tile.
__global__ void sgemm64(const float* __restrict__ A, const float* __restrict__ Bm,
                        float* __restrict__ Cm, int M, int N, int K) {
    __shared__ float As[16][64];
    __shared__ float Bs[16][64];
    int tid = threadIdx.x;
    int tx = tid & 15, ty = tid >> 4;
    int n0 = blockIdx.x * 64;
    int m0 = blockIdx.y * 64;

    float acc[4][4];
#pragma unroll
    for (int i = 0; i < 4; i++)
#pragma unroll
        for (int j = 0; j < 4; j++) acc[i][j] = 0.f;

    for (int k0 = 0; k0 < K; k0 += 16) {
#pragma unroll
        for (int q = 0; q < 4; q++) {
            int l = tid + q * 256;
            int m = l >> 4, ka = l & 15;
            As[ka][m] = A[(size_t)(m0 + m) * K + k0 + ka];
            int kb = l >> 6, n = l & 63;
            Bs[kb][n] = Bm[(size_t)(k0 + kb) * N + n0 + n];
        }
        __syncthreads();
#pragma unroll
        for (int kk = 0; kk < 16; kk++) {
            float a0 = As[kk][ty], a1 = As[kk][ty + 16], a2 = As[kk][ty + 32], a3 = As[kk][ty + 48];
            float b0 = Bs[kk][tx], b1 = Bs[kk][tx + 16], b2 = Bs[kk][tx + 32], b3 = Bs[kk][tx + 48];
            acc[0][0] += a0 * b0; acc[0][1] += a0 * b1; acc[0][2] += a0 * b2; acc[0][3] += a0 * b3;
            acc[1][0] += a1 * b0; acc[1][1] += a1 * b1; acc[1][2] += a1 * b2; acc[1][3] += a1 * b3;
            acc[2][0] += a2 * b0; acc[2][1] += a2 * b1; acc[2][2] += a2 * b2; acc[2][3] += a2 * b3;
            acc[3][0] += a3 * b0; acc[3][1] += a3 * b1; acc[3][2] += a3 * b2; acc[3][3] += a3 * b3;
        }
        __syncthreads();
    }
#pragma unroll
    for (int i = 0; i < 4; i++)
#pragma unroll
        for (int j = 0; j < 4; j++)
            Cm[(size_t)(m0 + ty + 16 * i) * N + n0 + tx + 16 * j] = acc[i][j];
}

__device__ __forceinline__ float sigmoidf_(float z) {
    return 1.0f / (1.0f + __expf(-z));
}

// ---------------- time-mix token shift (in place on kvr) ----------------
__global__ void mix1_kernel(float* __restrict__ kvr, const float* __restrict__ x,
                            const float* __restrict__ tmk, const float* __restrict__ tmv,
                            const float* __restrict__ tmr) {
    size_t idx = (size_t)blockIdx.x * blockDim.x + threadIdx.x;  // over BT_*C_
    int rem = (int)(idx & ((size_t)T_ * C_ - 1));
    int b = (int)(idx >> 21);  // T_*C_ = 2^21
    int t = rem >> 10;
    int c = rem & 1023;
    float xp = (t > 0) ? x[idx - C_] : x[idx];
    size_t kbase = ((size_t)b * T_ + t) * C3_;
    float mk = tmk[c], mv = tmv[c], mr = tmr[c];
    float kx = kvr[kbase + c];
    float vx = kvr[kbase + C_ + c];
    float rx = kvr[kbase + 2 * C_ + c];
    kvr[kbase + c]          = kx * mk + xp * (1.f - mk);
    kvr[kbase + C_ + c]     = vx * mv + xp * (1.f - mv);
    kvr[kbase + 2 * C_ + c] = sigmoidf_(rx * mr + xp * (1.f - mr));
}

// ---------------- WKV recurrence: one thread per (b,c) ----------------
__global__ void wkv_kernel(const float* __restrict__ kvr,
                           const float* __restrict__ wd, const float* __restrict__ uf,
                           float* __restrict__ y, float* __restrict__ state_out) {
    int idx = blockIdx.x * blockDim.x + threadIdx.x;
    if (idx >= B_ * C_) return;
    int b = idx >> 10;
    int c = idx & 1023;
    float w = wd[c], u = uf[c];
    float aa = 0.f, bb = -1e38f;
    const float* base = kvr + (size_t)b * T_ * C3_ + c;
    float* yb = y + (size_t)b * T_ * C_ + c;
#pragma unroll 1
    for (int t = 0; t < T_; t++) {
        float kk = base[(size_t)t * C3_];
        float vv = base[(size_t)t * C3_ + C_];
        float ww = u + kk;
        float p = fmaxf(bb, ww);
        float e1 = __expf(bb - p);
        float e2 = __expf(ww - p);
        yb[(size_t)t * C_] = (e1 * aa + e2 * vv) / (e1 + e2 + 1e-8f);
        ww = w + bb;
        p = fmaxf(ww, kk);
        e1 = __expf(ww - p);
        e2 = __expf(kk - p);
        aa = e1 * aa + e2 * vv;
        bb = p + __logf(e1 + e2 + 1e-8f);
    }
    state_out[(size_t)(b * C_ + c) * 2]     = aa;
    state_out[(size_t)(b * C_ + c) * 2 + 1] = bb;
}

// ---------------- x1 = x + r * y ----------------
__global__ void xres1_kernel(const float* __restrict__ x, const float* __restrict__ kvr,
                             const float* __restrict__ y, float* __restrict__ x1) {
    size_t idx = (size_t)blockIdx.x * blockDim.x + threadIdx.x;
    int rem = (int)(idx & ((size_t)T_ * C_ - 1));
    int b = (int)(idx >> 21);
    int t = rem >> 10;
    int c = rem & 1023;
    size_t kbase = ((size_t)b * T_ + t) * C3_;
    x1[idx] = x[idx] + kvr[kbase + 2 * C_ + c] * y[idx];
}

// ---------------- channel-mix hidden: h = relu(kk*cmk + xp*(1-cmk))^2, in place ----------------
__global__ void mix2_kernel(float* __restrict__ h, const float* __restrict__ x1,
                            const float* __restrict__ cmk) {
    size_t idx = (size_t)blockIdx.x * blockDim.x + threadIdx.x;  // over BT_*C4_
    int rem = (int)(idx & ((size_t)T_ * C4_ - 1));
    int b = (int)(idx >> 23);  // T_*C4_ = 2^23
    int t = rem >> 12;
    int j = rem & 4095;
    int c = j & 1023;
    int tp = (t > 0) ? (t - 1) : (T_ - 1);  // reference wraps t=0 to last token
    float xp = x1[((size_t)b * T_ + tp) * C_ + c];
    float mk = cmk[c];
    float kk = h[idx] * mk + xp * (1.f - mk);
    kk = fmaxf(kk, 0.f);
    h[idx] = kk * kk;
}

// ---------------- out = x1 + sigmoid(xn2*cmr + xp*(1-cmr)) * vv ----------------
__global__ void final_kernel(const float* __restrict__ x1, const float* __restrict__ xn2,
                             const float* __restrict__ vv, const float* __restrict__ cmr,
                             float* __restrict__ out) {
    size_t idx = (size_t)blockIdx.x * blockDim.x + threadIdx.x;
    int rem = (int)(idx & ((size_t)T_ * C_ - 1));
    int b = (int)(idx >> 21);
    int t = rem >> 10;
    int c = rem & 1023;
    int tp = (t > 0) ? (t - 1) : (T_ - 1);
    float xp = x1[((size_t)b * T_ + tp) * C_ + c];
    float mr = cmr[c];
    float rr = sigmoidf_(xn2[idx] * mr + xp * (1.f - mr));
    out[idx] = x1[idx] + rr * vv[idx];
}

// ---------------- host ----------------
extern "C" void kernel_launch(void* const* d_in, const int* in_sizes, int n_in,
                              void* d_out, int out_size) {
    const float* x    = (const float*)d_in[0];
    const float* wdec = (const float*)d_in[1];
    const float* ufst = (const float*)d_in[2];
    const float* W_tm = (const float*)d_in[3];
    const float* g1   = (const float*)d_in[4];
    const float* b1   = (const float*)d_in[5];
    const float* tmk  = (const float*)d_in[6];
    const float* tmv  = (const float*)d_in[7];
    const float* tmr  = (const float*)d_in[8];
    const float* W_cm = (const float*)d_in[9];
    const float* W_cp = (const float*)d_in[10];
    const float* g2   = (const float*)d_in[11];
    const float* b2   = (const float*)d_in[12];
    const float* cmk  = (const float*)d_in[13];
    const float* cmr  = (const float*)d_in[14];
    float* out = (float*)d_out;

    float *xn, *y, *x1, *kvr, *h;
    cudaGetSymbolAddress((void**)&xn,  g_xn);
    cudaGetSymbolAddress((void**)&y,   g_y);
    cudaGetSymbolAddress((void**)&x1,  g_x1);
    cudaGetSymbolAddress((void**)&kvr, g_kvr);
    cudaGetSymbolAddress((void**)&h,   g_h);

    float* state_out = out + (size_t)BT_ * C_;

    const int EW = 256;  // elementwise block
    size_t nxc = (size_t)BT_ * C_;      // 16,777,216
    size_t nh  = (size_t)BT_ * C4_;     // 67,108,864

    // 1. LayerNorm 1
    ln_kernel<<<BT_, 256>>>(x, g1, b1, xn);
    // 2. kvr = xn @ W_tm
    sgemm64<<<dim3(C3_ / 64, BT_ / 64), 256>>>(xn, W_tm, kvr, BT_, C3_, C_);
    // 3. token-shift mixing (in place)
    mix1_kernel<<<(unsigned)(nxc / EW), EW>>>(kvr, x, tmk, tmv, tmr);
    // 4. WKV recurrence
    wkv_kernel<<<(B_ * C_) / 64, 64>>>(kvr, wdec, ufst, y, state_out);
    // 5. x1 = x + r*y
    xres1_kernel<<<(unsigned)(nxc / EW), EW>>>(x, kvr, y, x1);
    // 6. LayerNorm 2
    ln_kernel<<<BT_, 256>>>(x1, g2, b2, xn);
    // 7. h = xn2 @ W_cm
    sgemm64<<<dim3(C4_ / 64, BT_ / 64), 256>>>(xn, W_cm, h, BT_, C4_, C_);
    // 8. hidden mix + relu^2 (in place)
    mix2_kernel<<<(unsigned)(nh / EW), EW>>>(h, x1, cmk);
    // 9. vv = h @ W_cp   (reuse y buffer)
    sgemm64<<<dim3(C_ / 64, BT_ / 64), 256>>>(h, W_cp, y, BT_, C_, C4_);
    // 10. out = x1 + rr * vv
    final_kernel<<<(unsigned)(nxc / EW), EW>>>(x1, xn, y, cmr, out);
}

// round 4
// speedup vs baseline: 5.0105x; 5.0105x over previous
#include <cuda_runtime.h>
#include <cstdint>
#include <cstddef>

// Problem constants
#define B_ 8
#define T_ 2048
#define C_ 1024
#define BT_ (B_ * T_)        // 16384
#define C3_ (3 * C_)         // 3072
#define C4_ (4 * C_)         // 4096

// ---------------- scratch (static device globals; no allocation) ----------------
__device__ float g_xn[(size_t)BT_ * C_];    // xn1, later xn2
__device__ float g_y[(size_t)BT_ * C_];     // wkv y, later vv
__device__ float g_x1[(size_t)BT_ * C_];    // x after time mixing
__device__ float g_kvr[(size_t)BT_ * C3_];  // kvr (k,v,r mixed in place)
__device__ float g_h[(size_t)BT_ * C4_];    // channel-mix hidden

// ---------------- LayerNorm ----------------
__global__ void ln_kernel(const float* __restrict__ x,
                          const float* __restrict__ g,
                          const float* __restrict__ b,
                          float* __restrict__ out) {
    size_t row = blockIdx.x;
    int tid = threadIdx.x;  // 256 threads, 4 floats each
    const float4* xr = reinterpret_cast<const float4*>(x + row * C_);
    float4 v = xr[tid];
    float s = v.x + v.y + v.z + v.w;
    float s2 = v.x * v.x + v.y * v.y + v.z * v.z + v.w * v.w;

    __shared__ float sa[8], sb[8];
    for (int o = 16; o > 0; o >>= 1) {
        s  += __shfl_down_sync(0xffffffffu, s, o);
        s2 += __shfl_down_sync(0xffffffffu, s2, o);
    }
    int w = tid >> 5, l = tid & 31;
    if (l == 0) { sa[w] = s; sb[w] = s2; }
    __syncthreads();
    if (w == 0) {
        s  = (l < 8) ? sa[l] : 0.f;
        s2 = (l < 8) ? sb[l] : 0.f;
        for (int o = 4; o > 0; o >>= 1) {
            s  += __shfl_down_sync(0xffffffffu, s, o);
            s2 += __shfl_down_sync(0xffffffffu, s2, o);
        }
        if (l == 0) { sa[0] = s; sb[0] = s2; }
    }
    __syncthreads();
    float mean = sa[0] * (1.0f / C_);
    float var = sb[0] * (1.0f / C_) - mean * mean;
    float rstd = rsqrtf(var + 1e-5f);

    float4 gg = reinterpret_cast<const float4*>(g)[tid];
    float4 bb = reinterpret_cast<const float4*>(b)[tid];
    float4 o;
    o.x = (v.x - mean) * rstd * gg.x + bb.x;
    o.y = (v.y - mean) * rstd * gg.y + bb.y;
    o.z = (v.z - mean) * rstd * gg.z + bb.z;
    o.w = (v.w - mean) * rstd * gg.w + bb.w;
    reinterpret_cast<float4*>(out + row * C_)[tid] = o;
}

// ---------------- TF32 tensor-core GEMM ----------------
__device__ __forceinline__ uint32_t cvt_tf32(float f) {
    uint32_t u;
    asm("cvt.rna.tf32.f32 %0, %1;" : "=r"(u) : "f"(f));
    return u;
}
__device__ __forceinline__ float4 cvt4(float4 v) {
    float4 r;
    r.x = __uint_as_float(cvt_tf32(v.x));
    r.y = __uint_as_float(cvt_tf32(v.y));
    r.z = __uint_as_float(cvt_tf32(v.z));
    r.w = __uint_as_float(cvt_tf32(v.w));
    return r;
}
__device__ __forceinline__ void mma_tf32(float* c, const uint32_t* a, const uint32_t* b) {
    asm volatile(
        "mma.sync.aligned.m16n8k8.row.col.f32.tf32.tf32.f32 "
        "{%0,%1,%2,%3}, {%4,%5,%6,%7}, {%8,%9}, {%0,%1,%2,%3};\n"
        : "+f"(c[0]), "+f"(c[1]), "+f"(c[2]), "+f"(c[3])
        : "r"(a[0]), "r"(a[1]), "r"(a[2]), "r"(a[3]), "r"(b[0]), "r"(b[1]));
}

// C[M,N] = A[M,K] @ B[K,N], row-major fp32 in/out, tf32 mma inside.
// 128x128 tile, BK=16, 256 threads (8 warps = 4x2, each 32x64 warp tile).
__global__ __launch_bounds__(256, 2)
void gemm_tf32(const float* __restrict__ A, const float* __restrict__ B,
               float* __restrict__ C, int M, int N, int K) {
    __shared__ float As[2][128][20];   // [m][k], stride 20 -> conflict-free frag loads
    __shared__ float Bs[2][16][136];   // [k][n], stride 136 -> conflict-free frag loads

    const int tid = threadIdx.x;
    const int lane = tid & 31;
    const int wid = tid >> 5;
    const int wm = (wid & 3) * 32;     // warp m offset
    const int wn = (wid >> 2) * 64;    // warp n offset
    const int g = lane >> 2;           // groupID (0..7)
    const int tig = lane & 3;          // thread-in-group (0..3)

    const int m0 = blockIdx.y * 128;
    const int n0 = blockIdx.x * 128;

    // global->shared load mapping
    const int am = tid >> 2;           // 0..63, rows am and am+64
    const int ak = (tid & 3) * 4;      // 0,4,8,12
    const int bk = tid >> 5;           // 0..7, rows bk and bk+8
    const int bn = (tid & 31) * 4;     // 0..124

    const float* Ap = A + (size_t)(m0 + am) * K + ak;
    const float* Bp = B + (size_t)bk * N + n0 + bn;

    float acc[2][8][4];
#pragma unroll
    for (int i = 0; i < 2; i++)
#pragma unroll
        for (int j = 0; j < 8; j++)
#pragma unroll
            for (int v = 0; v < 4; v++) acc[i][j][v] = 0.f;

    float4 ra0, ra1, rb0, rb1;

    // prologue: load + store tile 0
    ra0 = *(const float4*)(Ap);
    ra1 = *(const float4*)(Ap + (size_t)64 * K);
    rb0 = *(const float4*)(Bp);
    rb1 = *(const float4*)(Bp + (size_t)8 * N);
    *(float4*)&As[0][am][ak]      = cvt4(ra0);
    *(float4*)&As[0][am + 64][ak] = cvt4(ra1);
    *(float4*)&Bs[0][bk][bn]      = cvt4(rb0);
    *(float4*)&Bs[0][bk + 8][bn]  = cvt4(rb1);
    __syncthreads();

    const int ntiles = K >> 4;
    for (int kt = 0; kt < ntiles; kt++) {
        const int cur = kt & 1;
        if (kt + 1 < ntiles) {
            const float* Ap2 = Ap + (size_t)(kt + 1) * 16;
            const float* Bp2 = Bp + (size_t)(kt + 1) * 16 * N;
            ra0 = *(const float4*)(Ap2);
            ra1 = *(const float4*)(Ap2 + (size_t)64 * K);
            rb0 = *(const float4*)(Bp2);
            rb1 = *(const float4*)(Bp2 + (size_t)8 * N);
        }
#pragma unroll
        for (int ks = 0; ks < 2; ks++) {
            const int kk = ks * 8;
            uint32_t a[2][4], b[8][2];
#pragma unroll
            for (int i = 0; i < 2; i++) {
                const int mr = wm + i * 16 + g;
                a[i][0] = __float_as_uint(As[cur][mr][kk + tig]);
                a[i][1] = __float_as_uint(As[cur][mr + 8][kk + tig]);
                a[i][2] = __float_as_uint(As[cur][mr][kk + tig + 4]);
                a[i][3] = __float_as_uint(As[cur][mr + 8][kk + tig + 4]);
            }
#pragma unroll
            for (int j = 0; j < 8; j++) {
                const int nc = wn + j * 8 + g;
                b[j][0] = __float_as_uint(Bs[cur][kk + tig][nc]);
                b[j][1] = __float_as_uint(Bs[cur][kk + tig + 4][nc]);
            }
#pragma unroll
            for (int i = 0; i < 2; i++)
#pragma unroll
                for (int j = 0; j < 8; j++)
                    mma_tf32(acc[i][j], a[i], b[j]);
        }
        if (kt + 1 < ntiles) {
            const int nxt = cur ^ 1;
            *(float4*)&As[nxt][am][ak]      = cvt4(ra0);
            *(float4*)&As[nxt][am + 64][ak] = cvt4(ra1);
            *(float4*)&Bs[nxt][bk][bn]      = cvt4(rb0);
            *(float4*)&Bs[nxt][bk + 8][bn]  = cvt4(rb1);
        }
        __syncthreads();
    }

    // epilogue
#pragma unroll
    for (int i = 0; i < 2; i++) {
#pragma unroll
        for (int j = 0; j < 8; j++) {
            int row = m0 + wm + i * 16 + g;
            int col = n0 + wn + j * 8 + 2 * tig;
            float2 v01 = make_float2(acc[i][j][0], acc[i][j][1]);
            float2 v23 = make_float2(acc[i][j][2], acc[i][j][3]);
            *(float2*)&C[(size_t)row * N + col]       = v01;
            *(float2*)&C[(size_t)(row + 8) * N + col] = v23;
        }
    }
}

__device__ __forceinline__ float sigmoidf_(float z) {
    return 1.0f / (1.0f + __expf(-z));
}

// ---------------- time-mix token shift (in place on kvr) ----------------
__global__ void mix1_kernel(float* __restrict__ kvr, const float* __restrict__ x,
                            const float* __restrict__ tmk, const float* __restrict__ tmv,
                            const float* __restrict__ tmr) {
    size_t idx = (size_t)blockIdx.x * blockDim.x + threadIdx.x;  // over BT_*C_
    int rem = (int)(idx & ((size_t)T_ * C_ - 1));
    int b = (int)(idx >> 21);  // T_*C_ = 2^21
    int t = rem >> 10;
    int c = rem & 1023;
    float xp = (t > 0) ? x[idx - C_] : x[idx];
    size_t kbase = ((size_t)b * T_ + t) * C3_;
    float mk = tmk[c], mv = tmv[c], mr = tmr[c];
    float kx = kvr[kbase + c];
    float vx = kvr[kbase + C_ + c];
    float rx = kvr[kbase + 2 * C_ + c];
    kvr[kbase + c]          = kx * mk + xp * (1.f - mk);
    kvr[kbase + C_ + c]     = vx * mv + xp * (1.f - mv);
    kvr[kbase + 2 * C_ + c] = sigmoidf_(rx * mr + xp * (1.f - mr));
}

// ---------------- WKV recurrence: one thread per (b,c), depth-8 prefetch ring --------
__global__ void wkv_kernel(const float* __restrict__ kvr,
                           const float* __restrict__ wd, const float* __restrict__ uf,
                           float* __restrict__ y, float* __restrict__ state_out) {
    int idx = blockIdx.x * blockDim.x + threadIdx.x;
    if (idx >= B_ * C_) return;
    int b = idx >> 10;
    int c = idx & 1023;
    float w = wd[c], u = uf[c];
    float aa = 0.f, bb = -1e38f;
    const float* base = kvr + (size_t)b * T_ * C3_ + c;
    float* yb = y + (size_t)b * T_ * C_ + c;

    const int D = 8;
    float kr[D], vr[D];
#pragma unroll
    for (int s = 0; s < D; s++) {
        kr[s] = base[(size_t)s * C3_];
        vr[s] = base[(size_t)s * C3_ + C_];
    }
#pragma unroll 1
    for (int t0 = 0; t0 < T_; t0 += D) {
#pragma unroll
        for (int s = 0; s < D; s++) {
            float kk = kr[s], vv = vr[s];
            int tp = t0 + s + D;
            if (tp < T_) {
                kr[s] = base[(size_t)tp * C3_];
                vr[s] = base[(size_t)tp * C3_ + C_];
            }
            float ww = u + kk;
            float p = fmaxf(bb, ww);
            float e1 = __expf(bb - p);
            float e2 = __expf(ww - p);
            yb[(size_t)(t0 + s) * C_] = (e1 * aa + e2 * vv) / (e1 + e2 + 1e-8f);
            ww = w + bb;
            p = fmaxf(ww, kk);
            e1 = __expf(ww - p);
            e2 = __expf(kk - p);
            aa = e1 * aa + e2 * vv;
            bb = p + __logf(e1 + e2 + 1e-8f);
        }
    }
    state_out[(size_t)(b * C_ + c) * 2]     = aa;
    state_out[(size_t)(b * C_ + c) * 2 + 1] = bb;
}

// ---------------- x1 = x + r * y ----------------
__global__ void xres1_kernel(const float* __restrict__ x, const float* __restrict__ kvr,
                             const float* __restrict__ y, float* __restrict__ x1) {
    size_t idx = (size_t)blockIdx.x * blockDim.x + threadIdx.x;
    int rem = (int)(idx & ((size_t)T_ * C_ - 1));
    int b = (int)(idx >> 21);
    int t = rem >> 10;
    int c = rem & 1023;
    size_t kbase = ((size_t)b * T_ + t) * C3_;
    x1[idx] = x[idx] + kvr[kbase + 2 * C_ + c] * y[idx];
}

// ---------------- channel-mix hidden: h = relu(kk*cmk + xp*(1-cmk))^2, in place ------
__global__ void mix2_kernel(float* __restrict__ h, const float* __restrict__ x1,
                            const float* __restrict__ cmk) {
    size_t idx = (size_t)blockIdx.x * blockDim.x + threadIdx.x;  // over BT_*C4_
    int rem = (int)(idx & ((size_t)T_ * C4_ - 1));
    int b = (int)(idx >> 23);  // T_*C4_ = 2^23
    int t = rem >> 12;
    int j = rem & 4095;
    int c = j & 1023;
    int tp = (t > 0) ? (t - 1) : (T_ - 1);  // reference wraps t=0 to last token
    float xp = x1[((size_t)b * T_ + tp) * C_ + c];
    float mk = cmk[c];
    float kk = h[idx] * mk + xp * (1.f - mk);
    kk = fmaxf(kk, 0.f);
    h[idx] = kk * kk;
}

// ---------------- out = x1 + sigmoid(xn2*cmr + xp*(1-cmr)) * vv ----------------
__global__ void final_kernel(const float* __restrict__ x1, const float* __restrict__ xn2,
                             const float* __restrict__ vv, const float* __restrict__ cmr,
                             float* __restrict__ out) {
    size_t idx = (size_t)blockIdx.x * blockDim.x + threadIdx.x;
    int rem = (int)(idx & ((size_t)T_ * C_ - 1));
    int b = (int)(idx >> 21);
    int t = rem >> 10;
    int c = rem & 1023;
    int tp = (t > 0) ? (t - 1) : (T_ - 1);
    float xp = x1[((size_t)b * T_ + tp) * C_ + c];
    float mr = cmr[c];
    float rr = sigmoidf_(xn2[idx] * mr + xp * (1.f - mr));
    out[idx] = x1[idx] + rr * vv[idx];
}

// ---------------- host ----------------
extern "C" void kernel_launch(void* const* d_in, const int* in_sizes, int n_in,
                              void* d_out, int out_size) {
    const float* x    = (const float*)d_in[0];
    const float* wdec = (const float*)d_in[1];
    const float* ufst = (const float*)d_in[2];
    const float* W_tm = (const float*)d_in[3];
    const float* g1   = (const float*)d_in[4];
    const float* b1   = (const float*)d_in[5];
    const float* tmk  = (const float*)d_in[6];
    const float* tmv  = (const float*)d_in[7];
    const float* tmr  = (const float*)d_in[8];
    const float* W_cm = (const float*)d_in[9];
    const float* W_cp = (const float*)d_in[10];
    const float* g2   = (const float*)d_in[11];
    const float* b2   = (const float*)d_in[12];
    const float* cmk  = (const float*)d_in[13];
    const float* cmr  = (const float*)d_in[14];
    float* out = (float*)d_out;

    float *xn, *y, *x1, *kvr, *h;
    cudaGetSymbolAddress((void**)&xn,  g_xn);
    cudaGetSymbolAddress((void**)&y,   g_y);
    cudaGetSymbolAddress((void**)&x1,  g_x1);
    cudaGetSymbolAddress((void**)&kvr, g_kvr);
    cudaGetSymbolAddress((void**)&h,   g_h);

    float* state_out = out + (size_t)BT_ * C_;

    const int EW = 256;
    size_t nxc = (size_t)BT_ * C_;      // 16,777,216
    size_t nh  = (size_t)BT_ * C4_;     // 67,108,864

    // 1. LayerNorm 1
    ln_kernel<<<BT_, 256>>>(x, g1, b1, xn);
    // 2. kvr = xn @ W_tm  (M=16384, N=3072, K=1024)
    gemm_tf32<<<dim3(C3_ / 128, BT_ / 128), 256>>>(xn, W_tm, kvr, BT_, C3_, C_);
    // 3. token-shift mixing (in place)
    mix1_kernel<<<(unsigned)(nxc / EW), EW>>>(kvr, x, tmk, tmv, tmr);
    // 4. WKV recurrence
    wkv_kernel<<<(B_ * C_) / 64, 64>>>(kvr, wdec, ufst, y, state_out);
    // 5. x1 = x + r*y
    xres1_kernel<<<(unsigned)(nxc / EW), EW>>>(x, kvr, y, x1);
    // 6. LayerNorm 2
    ln_kernel<<<BT_, 256>>>(x1, g2, b2, xn);
    // 7. h = xn2 @ W_cm  (M=16384, N=4096, K=1024)
    gemm_tf32<<<dim3(C4_ / 128, BT_ / 128), 256>>>(xn, W_cm, h, BT_, C4_, C_);
    // 8. hidden mix + relu^2 (in place)
    mix2_kernel<<<(unsigned)(nh / EW), EW>>>(h, x1, cmk);
    // 9. vv = h @ W_cp  (M=16384, N=1024, K=4096)  (reuse y buffer)
    gemm_tf32<<<dim3(C_ / 128, BT_ / 128), 256>>>(h, W_cp, y, BT_, C_, C4_);
    // 10. out = x1 + rr * vv
    final_kernel<<<(unsigned)(nxc / EW), EW>>>(x1, xn, y, cmr, out);
}

// round 9
// speedup vs baseline: 5.2758x; 1.0529x over previous
#include <cuda_runtime.h>
#include <cstdint>
#include <cstddef>

// Problem constants
#define B_ 8
#define T_ 2048
#define C_ 1024
#define BT_ (B_ * T_)        // 16384
#define C3_ (3 * C_)         // 3072
#define C4_ (4 * C_)         // 4096

// ---------------- scratch (static device globals; no allocation) ----------------
__device__ float g_xn[(size_t)BT_ * C_];    // xn1, later xn2
__device__ float g_x1[(size_t)BT_ * C_];    // x after time mixing
__device__ float g_kvr[(size_t)BT_ * C3_];  // raw kvr from GEMM1
__device__ float g_h[(size_t)BT_ * C4_];    // channel-mix hidden (post relu^2)

// =================== small helpers ===================
__device__ __forceinline__ uint32_t smem_u32(const void* p) {
    uint32_t a;
    asm("{ .reg .u64 t; cvta.to.shared.u64 t, %1; cvt.u32.u64 %0, t; }" : "=r"(a) : "l"(p));
    return a;
}
__device__ __forceinline__ void cp16(uint32_t s, const void* g) {
    asm volatile("cp.async.cg.shared.global [%0], [%1], 16;" :: "r"(s), "l"(g));
}
#define CP_COMMIT() asm volatile("cp.async.commit_group;" ::: "memory")
#define CP_WAIT2()  asm volatile("cp.async.wait_group 2;" ::: "memory")

__device__ __forceinline__ uint32_t cvt_tf32(float f) {
    uint32_t u;
    asm("cvt.rna.tf32.f32 %0, %1;" : "=r"(u) : "f"(f));
    return u;
}
__device__ __forceinline__ void mma_tf32(float* c, const uint32_t* a, const uint32_t* b) {
    asm volatile(
        "mma.sync.aligned.m16n8k8.row.col.f32.tf32.tf32.f32 "
        "{%0,%1,%2,%3}, {%4,%5,%6,%7}, {%8,%9}, {%0,%1,%2,%3};\n"
        : "+f"(c[0]), "+f"(c[1]), "+f"(c[2]), "+f"(c[3])
        : "r"(a[0]), "r"(a[1]), "r"(a[2]), "r"(a[3]), "r"(b[0]), "r"(b[1]));
}
__device__ __forceinline__ float sigmoidf_(float z) {
    return 1.0f / (1.0f + __expf(-z));
}

// =================== tf32 GEMM v2: 4-stage cp.async, fused epilogues ===================
// C[M,N] = A[M,K] @ B[K,N], row-major fp32. 128x128 tile, BK=16, 256 threads.
// Stage layout (floats): As 128x20 (2560), Bs 16x136 (2176) -> 4736 per stage, 4 stages.
#define STAGE_F 4736
#define SMEMB   (4 * STAGE_F * 4)   // 75776 bytes

// EPI: 0 = plain store; 1 = channel-mix hidden (relu(mix)^2); 2 = final residual
template <int EPI>
__device__ __forceinline__ void epi_store(float* __restrict__ Cm, int N, int row, int col,
                                          float v0, float v1,
                                          const float* __restrict__ x1p,
                                          const float* __restrict__ gate,
                                          const float* __restrict__ xn2) {
    if (EPI == 0) {
        *(float2*)&Cm[(size_t)row * N + col] = make_float2(v0, v1);
    } else if (EPI == 1) {
        int t = row & (T_ - 1);
        int rp = row - t + ((t > 0) ? t - 1 : T_ - 1);
        int c0 = col & (C_ - 1), c1 = (col + 1) & (C_ - 1);
        float xp0 = x1p[(size_t)rp * C_ + c0];
        float xp1 = x1p[(size_t)rp * C_ + c1];
        float mk0 = gate[c0], mk1 = gate[c1];
        float k0 = fmaxf((v0 - xp0) * mk0 + xp0, 0.f);
        float k1 = fmaxf((v1 - xp1) * mk1 + xp1, 0.f);
        *(float2*)&Cm[(size_t)row * N + col] = make_float2(k0 * k0, k1 * k1);
    } else {
        int t = row & (T_ - 1);
        int rp = row - t + ((t > 0) ? t - 1 : T_ - 1);
        float xp0 = x1p[(size_t)rp * C_ + col];
        float xp1 = x1p[(size_t)rp * C_ + col + 1];
        float g0 = gate[col], g1 = gate[col + 1];
        size_t o = (size_t)row * C_ + col;
        float r0 = sigmoidf_((xn2[o]     - xp0) * g0 + xp0);
        float r1 = sigmoidf_((xn2[o + 1] - xp1) * g1 + xp1);
        *(float2*)&Cm[o] = make_float2(x1p[o] + r0 * v0, x1p[o + 1] + r1 * v1);
    }
}

template <int EPI>
__global__ __launch_bounds__(256)
void gemm_tf32_v2(const float* __restrict__ A, const float* __restrict__ B,
                  float* __restrict__ Cm, int M, int N, int K,
                  const float* __restrict__ e_x1, const float* __restrict__ e_gate,
                  const float* __restrict__ e_xn2) {
    extern __shared__ float dsm[];
    const uint32_t su = smem_u32(dsm);

    const int tid = threadIdx.x;
    const int lane = tid & 31;
    const int wid = tid >> 5;
    const int wm = (wid & 3) * 32;     // warp m offset
    const int wn = (wid >> 2) * 64;    // warp n offset
    const int g = lane >> 2;           // 0..7
    const int tig = lane & 3;          // 0..3

    const int m0 = blockIdx.y * 128;
    const int n0 = blockIdx.x * 128;

    // producer mapping
    const int am = tid >> 2;           // 0..63 (+64)
    const int ak = (tid & 3) * 4;
    const int bk = tid >> 5;           // 0..7 (+8)
    const int bn = (tid & 31) * 4;

    const float* Ap = A + (size_t)(m0 + am) * K + ak;
    const float* Bp = B + (size_t)bk * N + n0 + bn;

    const uint32_t sa_off = (uint32_t)((am * 20 + ak) * 4);
    const uint32_t sa_off2 = (uint32_t)(((am + 64) * 20 + ak) * 4);
    const uint32_t sb_off = (uint32_t)(2560 * 4 + (bk * 136 + bn) * 4);
    const uint32_t sb_off2 = (uint32_t)(2560 * 4 + ((bk + 8) * 136 + bn) * 4);

    const int ntiles = K >> 4;

    // prologue: stages 0..2
#pragma unroll
    for (int s = 0; s < 3; s++) {
        uint32_t sb0 = su + s * (STAGE_F * 4);
        const float* ap = Ap + (size_t)s * 16;
        const float* bp = Bp + (size_t)s * 16 * N;
        cp16(sb0 + sa_off, ap);
        cp16(sb0 + sa_off2, ap + (size_t)64 * K);
        cp16(sb0 + sb_off, bp);
        cp16(sb0 + sb_off2, bp + (size_t)8 * N);
        CP_COMMIT();
    }

    float acc[2][8][4];
#pragma unroll
    for (int i = 0; i < 2; i++)
#pragma unroll
        for (int j = 0; j < 8; j++)
#pragma unroll
            for (int v = 0; v < 4; v++) acc[i][j][v] = 0.f;

    for (int kt = 0; kt < ntiles; kt++) {
        CP_WAIT2();
        __syncthreads();

        // issue stage kt+3 (overwrites stage consumed at iter kt-1)
        if (kt + 3 < ntiles) {
            int s = (kt + 3) & 3;
            uint32_t sb0 = su + s * (STAGE_F * 4);
            const float* ap = Ap + (size_t)(kt + 3) * 16;
            const float* bp = Bp + (size_t)(kt + 3) * 16 * N;
            cp16(sb0 + sa_off, ap);
            cp16(sb0 + sa_off2, ap + (size_t)64 * K);
            cp16(sb0 + sb_off, bp);
            cp16(sb0 + sb_off2, bp + (size_t)8 * N);
        }
        CP_COMMIT();

        const float* Asf = dsm + (kt & 3) * STAGE_F;
        const float* Bsf = Asf + 2560;
#pragma unroll
        for (int ks = 0; ks < 2; ks++) {
            const int kk = ks * 8;
            uint32_t a[2][4], b[8][2];
#pragma unroll
            for (int i = 0; i < 2; i++) {
                const int mr = wm + i * 16 + g;
                a[i][0] = cvt_tf32(Asf[mr * 20 + kk + tig]);
                a[i][1] = cvt_tf32(Asf[(mr + 8) * 20 + kk + tig]);
                a[i][2] = cvt_tf32(Asf[mr * 20 + kk + tig + 4]);
                a[i][3] = cvt_tf32(Asf[(mr + 8) * 20 + kk + tig + 4]);
            }
#pragma unroll
            for (int j = 0; j < 8; j++) {
                const int nc = wn + j * 8 + g;
                b[j][0] = cvt_tf32(Bsf[(kk + tig) * 136 + nc]);
                b[j][1] = cvt_tf32(Bsf[(kk + tig + 4) * 136 + nc]);
            }
#pragma unroll
            for (int i = 0; i < 2; i++)
#pragma unroll
                for (int j = 0; j < 8; j++)
                    mma_tf32(acc[i][j], a[i], b[j]);
        }
        __syncthreads();
    }

    // epilogue
#pragma unroll
    for (int i = 0; i < 2; i++) {
        const int row = m0 + wm + i * 16 + g;
#pragma unroll
        for (int j = 0; j < 8; j++) {
            const int col = n0 + wn + j * 8 + 2 * tig;
            epi_store<EPI>(Cm, N, row,     col, acc[i][j][0], acc[i][j][1], e_x1, e_gate, e_xn2);
            epi_store<EPI>(Cm, N, row + 8, col, acc[i][j][2], acc[i][j][3], e_x1, e_gate, e_xn2);
        }
    }
}

// =================== LayerNorm ===================
__global__ void ln_kernel(const float* __restrict__ x,
                          const float* __restrict__ g,
                          const float* __restrict__ b,
                          float* __restrict__ out) {
    size_t row = blockIdx.x;
    int tid = threadIdx.x;
    const float4* xr = reinterpret_cast<const float4*>(x + row * C_);
    float4 v = xr[tid];
    float s = v.x + v.y + v.z + v.w;
    float s2 = v.x * v.x + v.y * v.y + v.z * v.z + v.w * v.w;

    __shared__ float sa[8], sb[8];
    for (int o = 16; o > 0; o >>= 1) {
        s  += __shfl_down_sync(0xffffffffu, s, o);
        s2 += __shfl_down_sync(0xffffffffu, s2, o);
    }
    int w = tid >> 5, l = tid & 31;
    if (l == 0) { sa[w] = s; sb[w] = s2; }
    __syncthreads();
    if (w == 0) {
        s  = (l < 8) ? sa[l] : 0.f;
        s2 = (l < 8) ? sb[l] : 0.f;
        for (int o = 4; o > 0; o >>= 1) {
            s  += __shfl_down_sync(0xffffffffu, s, o);
            s2 += __shfl_down_sync(0xffffffffu, s2, o);
        }
        if (l == 0) { sa[0] = s; sb[0] = s2; }
    }
    __syncthreads();
    float mean = sa[0] * (1.0f / C_);
    float var = sb[0] * (1.0f / C_) - mean * mean;
    float rstd = rsqrtf(var + 1e-5f);

    float4 gg = reinterpret_cast<const float4*>(g)[tid];
    float4 bb = reinterpret_cast<const float4*>(b)[tid];
    float4 o;
    o.x = (v.x - mean) * rstd * gg.x + bb.x;
    o.y = (v.y - mean) * rstd * gg.y + bb.y;
    o.z = (v.z - mean) * rstd * gg.z + bb.z;
    o.w = (v.w - mean) * rstd * gg.w + bb.w;
    reinterpret_cast<float4*>(out + row * C_)[tid] = o;
}

// =================== WKV fused: mix1 + recurrence + xres1 ===================
__global__ void wkv_fused(const float* __restrict__ kvr, const float* __restrict__ x,
                          const float* __restrict__ tmk, const float* __restrict__ tmv,
                          const float* __restrict__ tmr,
                          const float* __restrict__ wd, const float* __restrict__ uf,
                          float* __restrict__ x1, float* __restrict__ state_out) {
    int idx = blockIdx.x * blockDim.x + threadIdx.x;
    if (idx >= B_ * C_) return;
    int b = idx >> 10;
    int c = idx & 1023;
    const float mk = tmk[c], mv = tmv[c], mr = tmr[c];
    const float w = wd[c], u = uf[c];
    float aa = 0.f, bb = -1e38f;

    const float* kb = kvr + (size_t)b * T_ * C3_ + c;  // k:+0  v:+C_  r:+2C_
    const float* xb = x + (size_t)b * T_ * C_ + c;
    float* ob = x1 + (size_t)b * T_ * C_ + c;

    const int D = 8;
    float kr[D], vr[D], rr[D], xr[D];
#pragma unroll
    for (int s = 0; s < D; s++) {
        kr[s] = kb[(size_t)s * C3_];
        vr[s] = kb[(size_t)s * C3_ + C_];
        rr[s] = kb[(size_t)s * C3_ + 2 * C_];
        xr[s] = xb[(size_t)s * C_];
    }
    float xp = xr[0];  // x_prev for t=0 is x[t=0]

#pragma unroll 1
    for (int t0 = 0; t0 < T_; t0 += D) {
#pragma unroll
        for (int s = 0; s < D; s++) {
            float kraw = kr[s], vraw = vr[s], rraw = rr[s], xt = xr[s];
            int tp = t0 + s + D;
            if (tp < T_) {
                kr[s] = kb[(size_t)tp * C3_];
                vr[s] = kb[(size_t)tp * C3_ + C_];
                rr[s] = kb[(size_t)tp * C3_ + 2 * C_];
                xr[s] = xb[(size_t)tp * C_];
            }
            // token-shift mixing
            float km = (kraw - xp) * mk + xp;
            float vm = (vraw - xp) * mv + xp;
            float rm = (rraw - xp) * mr + xp;
            float rsg = __fdividef(1.f, 1.f + __expf(-rm));
            // y from previous state
            float ww = u + km;
            float d1 = bb - ww;                 // e1=exp(bb-p), e2=exp(ww-p); one is 1
            float e  = __expf(-fabsf(d1));
            float e1 = (d1 >= 0.f) ? 1.f : e;
            float e2 = (d1 >= 0.f) ? e : 1.f;
            float y  = __fdividef(e1 * aa + e2 * vm, e1 + e2 + 1e-8f);
            ob[(size_t)(t0 + s) * C_] = xt + rsg * y;
            // state update
            float wwb = w + bb;
            float d2 = wwb - km;
            float ee = __expf(-fabsf(d2));
            float f1 = (d2 >= 0.f) ? 1.f : ee;  // exp(wwb - p)
            float f2 = (d2 >= 0.f) ? ee : 1.f;  // exp(km - p)
            float p  = fmaxf(wwb, km);
            aa = f1 * aa + f2 * vm;
            bb = p + __logf(f1 + f2 + 1e-8f);
            xp = xt;
        }
    }
    state_out[(size_t)(b * C_ + c) * 2]     = aa;
    state_out[(size_t)(b * C_ + c) * 2 + 1] = bb;
}

// =================== host ===================
extern "C" void kernel_launch(void* const* d_in, const int* in_sizes, int n_in,
                              void* d_out, int out_size) {
    const float* x    = (const float*)d_in[0];
    const float* wdec = (const float*)d_in[1];
    const float* ufst = (const float*)d_in[2];
    const float* W_tm = (const float*)d_in[3];
    const float* g1   = (const float*)d_in[4];
    const float* b1   = (const float*)d_in[5];
    const float* tmk  = (const float*)d_in[6];
    const float* tmv  = (const float*)d_in[7];
    const float* tmr  = (const float*)d_in[8];
    const float* W_cm = (const float*)d_in[9];
    const float* W_cp = (const float*)d_in[10];
    const float* g2   = (const float*)d_in[11];
    const float* b2   = (const float*)d_in[12];
    const float* cmk  = (const float*)d_in[13];
    const float* cmr  = (const float*)d_in[14];
    float* out = (float*)d_out;

    float *xn, *x1, *kvr, *h;
    cudaGetSymbolAddress((void**)&xn,  g_xn);
    cudaGetSymbolAddress((void**)&x1,  g_x1);
    cudaGetSymbolAddress((void**)&kvr, g_kvr);
    cudaGetSymbolAddress((void**)&h,   g_h);

    float* state_out = out + (size_t)BT_ * C_;

    cudaFuncSetAttribute(gemm_tf32_v2<0>, cudaFuncAttributeMaxDynamicSharedMemorySize, SMEMB);
    cudaFuncSetAttribute(gemm_tf32_v2<1>, cudaFuncAttributeMaxDynamicSharedMemorySize, SMEMB);
    cudaFuncSetAttribute(gemm_tf32_v2<2>, cudaFuncAttributeMaxDynamicSharedMemorySize, SMEMB);

    // 1. LayerNorm 1
    ln_kernel<<<BT_, 256>>>(x, g1, b1, xn);
    // 2. kvr = xn @ W_tm   (M=16384, N=3072, K=1024)
    gemm_tf32_v2<0><<<dim3(C3_ / 128, BT_ / 128), 256, SMEMB>>>(
        xn, W_tm, kvr, BT_, C3_, C_, nullptr, nullptr, nullptr);
    // 3. WKV fused (token-shift mix + recurrence + residual) -> x1, state
    wkv_fused<<<(B_ * C_) / 64, 64>>>(kvr, x, tmk, tmv, tmr, wdec, ufst, x1, state_out);
    // 4. LayerNorm 2
    ln_kernel<<<BT_, 256>>>(x1, g2, b2, xn);
    // 5. h = relu(mix(xn2 @ W_cm))^2   (fused epilogue, M=16384, N=4096, K=1024)
    gemm_tf32_v2<1><<<dim3(C4_ / 128, BT_ / 128), 256, SMEMB>>>(
        xn, W_cm, h, BT_, C4_, C_, x1, cmk, nullptr);
    // 6. out = x1 + sigmoid(mix(xn2)) * (h @ W_cp)   (fused epilogue, M=16384, N=1024, K=4096)
    gemm_tf32_v2<2><<<dim3(C_ / 128, BT_ / 128), 256, SMEMB>>>(
        h, W_cp, out, BT_, C_, C4_, x1, cmr, xn);
}

// round 11
// speedup vs baseline: 9.9395x; 1.8840x over previous
#include <cuda_runtime.h>
#include <cuda_fp16.h>
#include <cstdint>
#include <cstddef>

// Problem constants
#define B_ 8
#define T_ 2048
#define C_ 1024
#define BT_ (B_ * T_)        // 16384
#define C3_ (3 * C_)         // 3072
#define C4_ (4 * C_)         // 4096

// ---------------- scratch (static device globals; no allocation) ----------------
__device__ float  g_x1[(size_t)BT_ * C_];    // x after time mixing
__device__ float  g_kvr[(size_t)BT_ * C3_];  // raw kvr from GEMM1 (fp32)
__device__ __half g_xnh[(size_t)BT_ * C_];   // LN output (fp16), xn1 then xn2
__device__ __half g_hh[(size_t)BT_ * C4_];   // channel-mix hidden (fp16, post relu^2)
__device__ __half g_wtm[(size_t)C3_ * C_];   // W_tm^T fp16  [3C][C]
__device__ __half g_wcm[(size_t)C4_ * C_];   // W_cm^T fp16  [4C][C]
__device__ __half g_wcp[(size_t)C_ * C4_];   // W_cp^T fp16  [C][4C]

// =================== small helpers ===================
__device__ __forceinline__ uint32_t smem_u32(const void* p) {
    uint32_t a;
    asm("{ .reg .u64 t; cvta.to.shared.u64 t, %1; cvt.u32.u64 %0, t; }" : "=r"(a) : "l"(p));
    return a;
}
__device__ __forceinline__ void cp16(uint32_t s, const void* g) {
    asm volatile("cp.async.cg.shared.global [%0], [%1], 16;" :: "r"(s), "l"(g));
}
#define CP_COMMIT() asm volatile("cp.async.commit_group;" ::: "memory")
#define CP_WAIT2()  asm volatile("cp.async.wait_group 2;" ::: "memory")

__device__ __forceinline__ void ldsm4(uint32_t* r, uint32_t addr) {
    asm volatile("ldmatrix.sync.aligned.m8n8.x4.shared.b16 {%0,%1,%2,%3}, [%4];"
                 : "=r"(r[0]), "=r"(r[1]), "=r"(r[2]), "=r"(r[3]) : "r"(addr));
}
__device__ __forceinline__ void mma_f16(float* c, const uint32_t* a, const uint32_t* b) {
    asm volatile(
        "mma.sync.aligned.m16n8k16.row.col.f32.f16.f16.f32 "
        "{%0,%1,%2,%3}, {%4,%5,%6,%7}, {%8,%9}, {%0,%1,%2,%3};\n"
        : "+f"(c[0]), "+f"(c[1]), "+f"(c[2]), "+f"(c[3])
        : "r"(a[0]), "r"(a[1]), "r"(a[2]), "r"(a[3]), "r"(b[0]), "r"(b[1]));
}
__device__ __forceinline__ float sigmoidf_(float z) {
    return 1.0f / (1.0f + __expf(-z));
}

// =================== fp16 tensor GEMM, 4-stage cp.async, ldmatrix, fused epilogues ====
// C[M,N] = A[M,K] @ B[K,N]; A fp16 [M][K] row-major, Bt fp16 [N][K] (pre-transposed).
// CTA tile 128x128, BK=32, 256 threads (8 warps = 4x2, warp tile 32x64).
// SMEM rows: 64B data + 16B pad = 80B stride (conflict-free ldmatrix phases).
#define ROWB   80
#define TILEB  (128 * ROWB)      // 10240
#define STAGEB (2 * TILEB)       // 20480
#define SMEMB  (4 * STAGEB)      // 81920

// EPI: 0 = plain fp32 store (kvr); 1 = channel-mix relu^2 -> fp16; 2 = final residual fp32
template <int EPI>
__device__ __forceinline__ void epi2(void* __restrict__ Cout, int N, int row, int col,
                                     float v0, float v1,
                                     const float* __restrict__ x1p,
                                     const float* __restrict__ gate,
                                     const __half* __restrict__ xn2) {
    if (EPI == 0) {
        *(float2*)&((float*)Cout)[(size_t)row * N + col] = make_float2(v0, v1);
    } else if (EPI == 1) {
        int t = row & (T_ - 1);
        int rp = row - t + ((t > 0) ? t - 1 : T_ - 1);
        int c0 = col & (C_ - 1), c1 = (col + 1) & (C_ - 1);
        float xp0 = x1p[(size_t)rp * C_ + c0];
        float xp1 = x1p[(size_t)rp * C_ + c1];
        float k0 = fmaxf((v0 - xp0) * gate[c0] + xp0, 0.f);
        float k1 = fmaxf((v1 - xp1) * gate[c1] + xp1, 0.f);
        *(__half2*)&((__half*)Cout)[(size_t)row * N + col] = __floats2half2_rn(k0 * k0, k1 * k1);
    } else {
        int t = row & (T_ - 1);
        int rp = row - t + ((t > 0) ? t - 1 : T_ - 1);
        float xp0 = x1p[(size_t)rp * C_ + col];
        float xp1 = x1p[(size_t)rp * C_ + col + 1];
        size_t o = (size_t)row * C_ + col;
        float r0 = sigmoidf_((__half2float(xn2[o])     - xp0) * gate[col]     + xp0);
        float r1 = sigmoidf_((__half2float(xn2[o + 1]) - xp1) * gate[col + 1] + xp1);
        *(float2*)&((float*)Cout)[o] = make_float2(x1p[o] + r0 * v0, x1p[o + 1] + r1 * v1);
    }
}

template <int EPI>
__global__ __launch_bounds__(256)
void gemm_f16(const __half* __restrict__ A, const __half* __restrict__ Bt,
              void* __restrict__ Cout, int M, int N, int K,
              const float* __restrict__ e_x1, const float* __restrict__ e_gate,
              const __half* __restrict__ e_xn2) {
    extern __shared__ char dsm[];
    const uint32_t su = smem_u32(dsm);

    const int tid = threadIdx.x;
    const int lane = tid & 31;
    const int wid = tid >> 5;
    const int wm = (wid & 3) * 32;     // warp m offset
    const int wn = (wid >> 2) * 64;    // warp n offset
    const int g = lane >> 2;           // 0..7
    const int tig = lane & 3;          // 0..3

    const int m0 = blockIdx.y * 128;
    const int n0 = blockIdx.x * 128;

    // producer mapping: 16B chunks; each thread: 2 A chunks + 2 B chunks per stage
    const int prow = tid >> 2;         // 0..63 (and +64)
    const int pseg = tid & 3;          // 0..3
    const __half* Ap0 = A + (size_t)(m0 + prow) * K + pseg * 8;
    const __half* Ap1 = A + (size_t)(m0 + prow + 64) * K + pseg * 8;
    const __half* Bp0 = Bt + (size_t)(n0 + prow) * K + pseg * 8;
    const __half* Bp1 = Bt + (size_t)(n0 + prow + 64) * K + pseg * 8;
    const uint32_t soA0 = (uint32_t)(prow * ROWB + pseg * 16);
    const uint32_t soA1 = (uint32_t)((prow + 64) * ROWB + pseg * 16);
    const uint32_t soB0 = TILEB + soA0;
    const uint32_t soB1 = TILEB + soA1;

    const int ntiles = K >> 5;         // BK = 32

    // prologue: stages 0..2
#pragma unroll
    for (int s = 0; s < 3; s++) {
        uint32_t sb0 = su + s * STAGEB;
        size_t koff = (size_t)s * 32;
        cp16(sb0 + soA0, Ap0 + koff);
        cp16(sb0 + soA1, Ap1 + koff);
        cp16(sb0 + soB0, Bp0 + koff);
        cp16(sb0 + soB1, Bp1 + koff);
        CP_COMMIT();
    }

    float acc[2][8][4];
#pragma unroll
    for (int i = 0; i < 2; i++)
#pragma unroll
        for (int j = 0; j < 8; j++)
#pragma unroll
            for (int v = 0; v < 4; v++) acc[i][j][v] = 0.f;

    // ldmatrix lane address components (within a 16-row x 32-half block)
    const uint32_t aro = (uint32_t)(lane & 15) * ROWB + (uint32_t)(lane >> 4) * 16;
    const uint32_t bro = (uint32_t)((lane & 7) + ((lane >> 4) << 3)) * ROWB
                       + (uint32_t)((lane >> 3) & 1) * 16;

    for (int kt = 0; kt < ntiles; kt++) {
        CP_WAIT2();
        __syncthreads();

        if (kt + 3 < ntiles) {
            uint32_t sb0 = su + ((kt + 3) & 3) * STAGEB;
            size_t koff = (size_t)(kt + 3) * 32;
            cp16(sb0 + soA0, Ap0 + koff);
            cp16(sb0 + soA1, Ap1 + koff);
            cp16(sb0 + soB0, Bp0 + koff);
            cp16(sb0 + soB1, Bp1 + koff);
        }
        CP_COMMIT();

        const uint32_t st = su + (kt & 3) * STAGEB;
#pragma unroll
        for (int ks = 0; ks < 2; ks++) {
            uint32_t a[2][4];
#pragma unroll
            for (int i = 0; i < 2; i++)
                ldsm4(a[i], st + (uint32_t)(wm + i * 16) * ROWB + ks * 32 + aro);
#pragma unroll
            for (int jj = 0; jj < 4; jj++) {
                uint32_t bfr[4];
                ldsm4(bfr, st + TILEB + (uint32_t)(wn + jj * 16) * ROWB + ks * 32 + bro);
#pragma unroll
                for (int i = 0; i < 2; i++) {
                    mma_f16(acc[i][2 * jj],     a[i], bfr + 0);
                    mma_f16(acc[i][2 * jj + 1], a[i], bfr + 2);
                }
            }
        }
        __syncthreads();
    }

    // epilogue
#pragma unroll
    for (int i = 0; i < 2; i++) {
        const int row = m0 + wm + i * 16 + g;
#pragma unroll
        for (int j = 0; j < 8; j++) {
            const int col = n0 + wn + j * 8 + 2 * tig;
            epi2<EPI>(Cout, N, row,     col, acc[i][j][0], acc[i][j][1], e_x1, e_gate, e_xn2);
            epi2<EPI>(Cout, N, row + 8, col, acc[i][j][2], acc[i][j][3], e_x1, e_gate, e_xn2);
        }
    }
}

// =================== weight convert + transpose: fp32 [K][N] -> fp16 [N][K] ===========
__global__ void wconv(const float* __restrict__ in, __half* __restrict__ out, int K, int N) {
    __shared__ float t[32][33];
    int n0 = blockIdx.x * 32, k0 = blockIdx.y * 32;
    int tx = threadIdx.x, ty = threadIdx.y;  // 32x8
#pragma unroll
    for (int q = 0; q < 4; q++)
        t[ty + q * 8][tx] = in[(size_t)(k0 + ty + q * 8) * N + n0 + tx];
    __syncthreads();
#pragma unroll
    for (int q = 0; q < 4; q++)
        out[(size_t)(n0 + ty + q * 8) * K + k0 + tx] = __float2half_rn(t[tx][ty + q * 8]);
}

// =================== LayerNorm -> fp16 ===================
__global__ void ln_kernel_h(const float* __restrict__ x,
                            const float* __restrict__ g,
                            const float* __restrict__ b,
                            __half* __restrict__ out) {
    size_t row = blockIdx.x;
    int tid = threadIdx.x;
    const float4* xr = reinterpret_cast<const float4*>(x + row * C_);
    float4 v = xr[tid];
    float s = v.x + v.y + v.z + v.w;
    float s2 = v.x * v.x + v.y * v.y + v.z * v.z + v.w * v.w;

    __shared__ float sa[8], sb[8];
    for (int o = 16; o > 0; o >>= 1) {
        s  += __shfl_down_sync(0xffffffffu, s, o);
        s2 += __shfl_down_sync(0xffffffffu, s2, o);
    }
    int w = tid >> 5, l = tid & 31;
    if (l == 0) { sa[w] = s; sb[w] = s2; }
    __syncthreads();
    if (w == 0) {
        s  = (l < 8) ? sa[l] : 0.f;
        s2 = (l < 8) ? sb[l] : 0.f;
        for (int o = 4; o > 0; o >>= 1) {
            s  += __shfl_down_sync(0xffffffffu, s, o);
            s2 += __shfl_down_sync(0xffffffffu, s2, o);
        }
        if (l == 0) { sa[0] = s; sb[0] = s2; }
    }
    __syncthreads();
    float mean = sa[0] * (1.0f / C_);
    float var = sb[0] * (1.0f / C_) - mean * mean;
    float rstd = rsqrtf(var + 1e-5f);

    float4 gg = reinterpret_cast<const float4*>(g)[tid];
    float4 bb = reinterpret_cast<const float4*>(b)[tid];
    __half2 h0 = __floats2half2_rn((v.x - mean) * rstd * gg.x + bb.x,
                                   (v.y - mean) * rstd * gg.y + bb.y);
    __half2 h1 = __floats2half2_rn((v.z - mean) * rstd * gg.z + bb.z,
                                   (v.w - mean) * rstd * gg.w + bb.w);
    __half2* op = reinterpret_cast<__half2*>(out + row * C_);
    op[tid * 2]     = h0;
    op[tid * 2 + 1] = h1;
}

// =================== WKV fused: mix1 + recurrence + xres1 ===================
__global__ void wkv_fused(const float* __restrict__ kvr, const float* __restrict__ x,
                          const float* __restrict__ tmk, const float* __restrict__ tmv,
                          const float* __restrict__ tmr,
                          const float* __restrict__ wd, const float* __restrict__ uf,
                          float* __restrict__ x1, float* __restrict__ state_out) {
    int idx = blockIdx.x * blockDim.x + threadIdx.x;
    if (idx >= B_ * C_) return;
    int b = idx >> 10;
    int c = idx & 1023;
    const float mk = tmk[c], mv = tmv[c], mr = tmr[c];
    const float w = wd[c], u = uf[c];
    float aa = 0.f, bb = -1e38f;

    const float* kb = kvr + (size_t)b * T_ * C3_ + c;  // k:+0  v:+C_  r:+2C_
    const float* xb = x + (size_t)b * T_ * C_ + c;
    float* ob = x1 + (size_t)b * T_ * C_ + c;

    const int D = 8;
    float kr[D], vr[D], rr[D], xr[D];
#pragma unroll
    for (int s = 0; s < D; s++) {
        kr[s] = kb[(size_t)s * C3_];
        vr[s] = kb[(size_t)s * C3_ + C_];
        rr[s] = kb[(size_t)s * C3_ + 2 * C_];
        xr[s] = xb[(size_t)s * C_];
    }
    float xp = xr[0];  // x_prev for t=0 is x[t=0]

#pragma unroll 1
    for (int t0 = 0; t0 < T_; t0 += D) {
#pragma unroll
        for (int s = 0; s < D; s++) {
            float kraw = kr[s], vraw = vr[s], rraw = rr[s], xt = xr[s];
            int tp = t0 + s + D;
            if (tp < T_) {
                kr[s] = kb[(size_t)tp * C3_];
                vr[s] = kb[(size_t)tp * C3_ + C_];
                rr[s] = kb[(size_t)tp * C3_ + 2 * C_];
                xr[s] = xb[(size_t)tp * C_];
            }
            float km = (kraw - xp) * mk + xp;
            float vm = (vraw - xp) * mv + xp;
            float rm = (rraw - xp) * mr + xp;
            float rsg = __fdividef(1.f, 1.f + __expf(-rm));
            float ww = u + km;
            float d1 = bb - ww;
            float e  = __expf(-fabsf(d1));
            float e1 = (d1 >= 0.f) ? 1.f : e;
            float e2 = (d1 >= 0.f) ? e : 1.f;
            float y  = __fdividef(e1 * aa + e2 * vm, e1 + e2 + 1e-8f);
            ob[(size_t)(t0 + s) * C_] = xt + rsg * y;
            float wwb = w + bb;
            float d2 = wwb - km;
            float ee = __expf(-fabsf(d2));
            float f1 = (d2 >= 0.f) ? 1.f : ee;
            float f2 = (d2 >= 0.f) ? ee : 1.f;
            float p  = fmaxf(wwb, km);
            aa = f1 * aa + f2 * vm;
            bb = p + __logf(f1 + f2 + 1e-8f);
            xp = xt;
        }
    }
    state_out[(size_t)(b * C_ + c) * 2]     = aa;
    state_out[(size_t)(b * C_ + c) * 2 + 1] = bb;
}

// =================== host ===================
extern "C" void kernel_launch(void* const* d_in, const int* in_sizes, int n_in,
                              void* d_out, int out_size) {
    const float* x    = (const float*)d_in[0];
    const float* wdec = (const float*)d_in[1];
    const float* ufst = (const float*)d_in[2];
    const float* W_tm = (const float*)d_in[3];
    const float* g1   = (const float*)d_in[4];
    const float* b1   = (const float*)d_in[5];
    const float* tmk  = (const float*)d_in[6];
    const float* tmv  = (const float*)d_in[7];
    const float* tmr  = (const float*)d_in[8];
    const float* W_cm = (const float*)d_in[9];
    const float* W_cp = (const float*)d_in[10];
    const float* g2   = (const float*)d_in[11];
    const float* b2   = (const float*)d_in[12];
    const float* cmk  = (const float*)d_in[13];
    const float* cmr  = (const float*)d_in[14];
    float* out = (float*)d_out;

    float *x1, *kvr;
    __half *xnh, *hh, *wtm, *wcm, *wcp;
    cudaGetSymbolAddress((void**)&x1,  g_x1);
    cudaGetSymbolAddress((void**)&kvr, g_kvr);
    cudaGetSymbolAddress((void**)&xnh, g_xnh);
    cudaGetSymbolAddress((void**)&hh,  g_hh);
    cudaGetSymbolAddress((void**)&wtm, g_wtm);
    cudaGetSymbolAddress((void**)&wcm, g_wcm);
    cudaGetSymbolAddress((void**)&wcp, g_wcp);

    float* state_out = out + (size_t)BT_ * C_;

    cudaFuncSetAttribute(gemm_f16<0>, cudaFuncAttributeMaxDynamicSharedMemorySize, SMEMB);
    cudaFuncSetAttribute(gemm_f16<1>, cudaFuncAttributeMaxDynamicSharedMemorySize, SMEMB);
    cudaFuncSetAttribute(gemm_f16<2>, cudaFuncAttributeMaxDynamicSharedMemorySize, SMEMB);

    dim3 wcb(32, 8);
    // 0. weight convert + transpose to fp16 [N][K]
    wconv<<<dim3(C3_ / 32, C_ / 32), wcb>>>(W_tm, wtm, C_, C3_);
    wconv<<<dim3(C4_ / 32, C_ / 32), wcb>>>(W_cm, wcm, C_, C4_);
    wconv<<<dim3(C_ / 32, C4_ / 32), wcb>>>(W_cp, wcp, C4_, C_);

    // 1. LayerNorm 1 -> fp16
    ln_kernel_h<<<BT_, 256>>>(x, g1, b1, xnh);
    // 2. kvr = xn1 @ W_tm   (M=16384, N=3072, K=1024), fp32 out
    gemm_f16<0><<<dim3(C3_ / 128, BT_ / 128), 256, SMEMB>>>(
        xnh, wtm, kvr, BT_, C3_, C_, nullptr, nullptr, nullptr);
    // 3. WKV fused (token-shift mix + recurrence + residual) -> x1, state
    wkv_fused<<<(B_ * C_) / 64, 64>>>(kvr, x, tmk, tmv, tmr, wdec, ufst, x1, state_out);
    // 4. LayerNorm 2 -> fp16
    ln_kernel_h<<<BT_, 256>>>(x1, g2, b2, xnh);
    // 5. h = relu(mix(xn2 @ W_cm))^2 -> fp16   (M=16384, N=4096, K=1024)
    gemm_f16<1><<<dim3(C4_ / 128, BT_ / 128), 256, SMEMB>>>(
        xnh, wcm, hh, BT_, C4_, C_, x1, cmk, nullptr);
    // 6. out = x1 + sigmoid(mix(xn2)) * (h @ W_cp)   (M=16384, N=1024, K=4096)
    gemm_f16<2><<<dim3(C_ / 128, BT_ / 128), 256, SMEMB>>>(
        hh, wcp, out, BT_, C_, C4_, x1, cmr, xnh);
}

// round 13
// speedup vs baseline: 11.5791x; 1.1650x over previous
#include <cuda_runtime.h>
#include <cuda_fp16.h>
#include <cstdint>
#include <cstddef>

// Problem constants
#define B_ 8
#define T_ 2048
#define C_ 1024
#define BT_ (B_ * T_)        // 16384
#define C3_ (3 * C_)         // 3072
#define C4_ (4 * C_)         // 4096

// ---------------- scratch (static device globals; no allocation) ----------------
__device__ float  g_x1[(size_t)BT_ * C_];    // x after time mixing
__device__ float  g_kvr[(size_t)BT_ * C3_];  // raw kvr from GEMM1 (fp32)
__device__ __half g_xnh[(size_t)BT_ * C_];   // LN output (fp16), xn1 then xn2
__device__ __half g_hh[(size_t)BT_ * C4_];   // channel-mix hidden (fp16, post relu^2)
__device__ __half g_wtm[(size_t)C3_ * C_];   // W_tm^T fp16  [3C][C]
__device__ __half g_wcm[(size_t)C4_ * C_];   // W_cm^T fp16  [4C][C]
__device__ __half g_wcp[(size_t)C_ * C4_];   // W_cp^T fp16  [C][4C]

// =================== small helpers ===================
__device__ __forceinline__ uint32_t smem_u32(const void* p) {
    uint32_t a;
    asm("{ .reg .u64 t; cvta.to.shared.u64 t, %1; cvt.u32.u64 %0, t; }" : "=r"(a) : "l"(p));
    return a;
}
__device__ __forceinline__ void cp16(uint32_t s, const void* g) {
    asm volatile("cp.async.cg.shared.global [%0], [%1], 16;" :: "r"(s), "l"(g));
}
#define CP_COMMIT() asm volatile("cp.async.commit_group;" ::: "memory")
#define CP_WAIT2()  asm volatile("cp.async.wait_group 2;" ::: "memory")
#define CP_WAIT3()  asm volatile("cp.async.wait_group 3;" ::: "memory")

__device__ __forceinline__ void ldsm4(uint32_t* r, uint32_t addr) {
    asm volatile("ldmatrix.sync.aligned.m8n8.x4.shared.b16 {%0,%1,%2,%3}, [%4];"
                 : "=r"(r[0]), "=r"(r[1]), "=r"(r[2]), "=r"(r[3]) : "r"(addr));
}
__device__ __forceinline__ void mma_f16(float* c, const uint32_t* a, const uint32_t* b) {
    asm volatile(
        "mma.sync.aligned.m16n8k16.row.col.f32.f16.f16.f32 "
        "{%0,%1,%2,%3}, {%4,%5,%6,%7}, {%8,%9}, {%0,%1,%2,%3};\n"
        : "+f"(c[0]), "+f"(c[1]), "+f"(c[2]), "+f"(c[3])
        : "r"(a[0]), "r"(a[1]), "r"(a[2]), "r"(a[3]), "r"(b[0]), "r"(b[1]));
}
__device__ __forceinline__ float sigmoidf_(float z) {
    return 1.0f / (1.0f + __expf(-z));
}

// =================== fp16 tensor GEMM, 4-stage cp.async, ldmatrix, fused epilogues ====
// C[M,N] = A[M,K] @ B[K,N]; A fp16 [M][K] row-major, Bt fp16 [N][K] (pre-transposed).
// CTA tile 128x128, BK=32, 256 threads (8 warps = 4x2, warp tile 32x64).
#define ROWB   80
#define TILEB  (128 * ROWB)      // 10240
#define STAGEB (2 * TILEB)       // 20480
#define SMEMB  (4 * STAGEB)      // 81920

// EPI: 0 = plain fp32 store (kvr); 1 = channel-mix relu^2 -> fp16; 2 = final residual fp32
template <int EPI>
__device__ __forceinline__ void epi2(void* __restrict__ Cout, int N, int row, int col,
                                     float v0, float v1,
                                     const float* __restrict__ x1p,
                                     const float* __restrict__ gate,
                                     const __half* __restrict__ xn2) {
    if (EPI == 0) {
        *(float2*)&((float*)Cout)[(size_t)row * N + col] = make_float2(v0, v1);
    } else if (EPI == 1) {
        int t = row & (T_ - 1);
        int rp = row - t + ((t > 0) ? t - 1 : T_ - 1);
        int c0 = col & (C_ - 1), c1 = (col + 1) & (C_ - 1);
        float xp0 = x1p[(size_t)rp * C_ + c0];
        float xp1 = x1p[(size_t)rp * C_ + c1];
        float k0 = fmaxf((v0 - xp0) * gate[c0] + xp0, 0.f);
        float k1 = fmaxf((v1 - xp1) * gate[c1] + xp1, 0.f);
        *(__half2*)&((__half*)Cout)[(size_t)row * N + col] = __floats2half2_rn(k0 * k0, k1 * k1);
    } else {
        int t = row & (T_ - 1);
        int rp = row - t + ((t > 0) ? t - 1 : T_ - 1);
        float xp0 = x1p[(size_t)rp * C_ + col];
        float xp1 = x1p[(size_t)rp * C_ + col + 1];
        size_t o = (size_t)row * C_ + col;
        float r0 = sigmoidf_((__half2float(xn2[o])     - xp0) * gate[col]     + xp0);
        float r1 = sigmoidf_((__half2float(xn2[o + 1]) - xp1) * gate[col + 1] + xp1);
        *(float2*)&((float*)Cout)[o] = make_float2(x1p[o] + r0 * v0, x1p[o + 1] + r1 * v1);
    }
}

template <int EPI>
__global__ __launch_bounds__(256)
void gemm_f16(const __half* __restrict__ A, const __half* __restrict__ Bt,
              void* __restrict__ Cout, int M, int N, int K,
              const float* __restrict__ e_x1, const float* __restrict__ e_gate,
              const __half* __restrict__ e_xn2) {
    extern __shared__ char dsm[];
    const uint32_t su = smem_u32(dsm);

    const int tid = threadIdx.x;
    const int lane = tid & 31;
    const int wid = tid >> 5;
    const int wm = (wid & 3) * 32;
    const int wn = (wid >> 2) * 64;
    const int g = lane >> 2;
    const int tig = lane & 3;

    const int m0 = blockIdx.y * 128;
    const int n0 = blockIdx.x * 128;

    const int prow = tid >> 2;
    const int pseg = tid & 3;
    const __half* Ap0 = A + (size_t)(m0 + prow) * K + pseg * 8;
    const __half* Ap1 = A + (size_t)(m0 + prow + 64) * K + pseg * 8;
    const __half* Bp0 = Bt + (size_t)(n0 + prow) * K + pseg * 8;
    const __half* Bp1 = Bt + (size_t)(n0 + prow + 64) * K + pseg * 8;
    const uint32_t soA0 = (uint32_t)(prow * ROWB + pseg * 16);
    const uint32_t soA1 = (uint32_t)((prow + 64) * ROWB + pseg * 16);
    const uint32_t soB0 = TILEB + soA0;
    const uint32_t soB1 = TILEB + soA1;

    const int ntiles = K >> 5;

#pragma unroll
    for (int s = 0; s < 3; s++) {
        uint32_t sb0 = su + s * STAGEB;
        size_t koff = (size_t)s * 32;
        cp16(sb0 + soA0, Ap0 + koff);
        cp16(sb0 + soA1, Ap1 + koff);
        cp16(sb0 + soB0, Bp0 + koff);
        cp16(sb0 + soB1, Bp1 + koff);
        CP_COMMIT();
    }

    float acc[2][8][4];
#pragma unroll
    for (int i = 0; i < 2; i++)
#pragma unroll
        for (int j = 0; j < 8; j++)
#pragma unroll
            for (int v = 0; v < 4; v++) acc[i][j][v] = 0.f;

    const uint32_t aro = (uint32_t)(lane & 15) * ROWB + (uint32_t)(lane >> 4) * 16;
    const uint32_t bro = (uint32_t)((lane & 7) + ((lane >> 4) << 3)) * ROWB
                       + (uint32_t)((lane >> 3) & 1) * 16;

    for (int kt = 0; kt < ntiles; kt++) {
        CP_WAIT2();
        __syncthreads();

        if (kt + 3 < ntiles) {
            uint32_t sb0 = su + ((kt + 3) & 3) * STAGEB;
            size_t koff = (size_t)(kt + 3) * 32;
            cp16(sb0 + soA0, Ap0 + koff);
            cp16(sb0 + soA1, Ap1 + koff);
            cp16(sb0 + soB0, Bp0 + koff);
            cp16(sb0 + soB1, Bp1 + koff);
        }
        CP_COMMIT();

        const uint32_t st = su + (kt & 3) * STAGEB;
#pragma unroll
        for (int ks = 0; ks < 2; ks++) {
            uint32_t a[2][4];
#pragma unroll
            for (int i = 0; i < 2; i++)
                ldsm4(a[i], st + (uint32_t)(wm + i * 16) * ROWB + ks * 32 + aro);
#pragma unroll
            for (int jj = 0; jj < 4; jj++) {
                uint32_t bfr[4];
                ldsm4(bfr, st + TILEB + (uint32_t)(wn + jj * 16) * ROWB + ks * 32 + bro);
#pragma unroll
                for (int i = 0; i < 2; i++) {
                    mma_f16(acc[i][2 * jj],     a[i], bfr + 0);
                    mma_f16(acc[i][2 * jj + 1], a[i], bfr + 2);
                }
            }
        }
        __syncthreads();
    }

#pragma unroll
    for (int i = 0; i < 2; i++) {
        const int row = m0 + wm + i * 16 + g;
#pragma unroll
        for (int j = 0; j < 8; j++) {
            const int col = n0 + wn + j * 8 + 2 * tig;
            epi2<EPI>(Cout, N, row,     col, acc[i][j][0], acc[i][j][1], e_x1, e_gate, e_xn2);
            epi2<EPI>(Cout, N, row + 8, col, acc[i][j][2], acc[i][j][3], e_x1, e_gate, e_xn2);
        }
    }
}

// =================== weight convert + transpose: fp32 [K][N] -> fp16 [N][K] ===========
__global__ void wconv(const float* __restrict__ in, __half* __restrict__ out, int K, int N) {
    __shared__ float t[32][33];
    int n0 = blockIdx.x * 32, k0 = blockIdx.y * 32;
    int tx = threadIdx.x, ty = threadIdx.y;  // 32x8
#pragma unroll
    for (int q = 0; q < 4; q++)
        t[ty + q * 8][tx] = in[(size_t)(k0 + ty + q * 8) * N + n0 + tx];
    __syncthreads();
#pragma unroll
    for (int q = 0; q < 4; q++)
        out[(size_t)(n0 + ty + q * 8) * K + k0 + tx] = __float2half_rn(t[tx][ty + q * 8]);
}

// =================== LayerNorm -> fp16 ===================
__global__ void ln_kernel_h(const float* __restrict__ x,
                            const float* __restrict__ g,
                            const float* __restrict__ b,
                            __half* __restrict__ out) {
    size_t row = blockIdx.x;
    int tid = threadIdx.x;
    const float4* xr = reinterpret_cast<const float4*>(x + row * C_);
    float4 v = xr[tid];
    float s = v.x + v.y + v.z + v.w;
    float s2 = v.x * v.x + v.y * v.y + v.z * v.z + v.w * v.w;

    __shared__ float sa[8], sb[8];
    for (int o = 16; o > 0; o >>= 1) {
        s  += __shfl_down_sync(0xffffffffu, s, o);
        s2 += __shfl_down_sync(0xffffffffu, s2, o);
    }
    int w = tid >> 5, l = tid & 31;
    if (l == 0) { sa[w] = s; sb[w] = s2; }
    __syncthreads();
    if (w == 0) {
        s  = (l < 8) ? sa[l] : 0.f;
        s2 = (l < 8) ? sb[l] : 0.f;
        for (int o = 4; o > 0; o >>= 1) {
            s  += __shfl_down_sync(0xffffffffu, s, o);
            s2 += __shfl_down_sync(0xffffffffu, s2, o);
        }
        if (l == 0) { sa[0] = s; sb[0] = s2; }
    }
    __syncthreads();
    float mean = sa[0] * (1.0f / C_);
    float var = sb[0] * (1.0f / C_) - mean * mean;
    float rstd = rsqrtf(var + 1e-5f);

    float4 gg = reinterpret_cast<const float4*>(g)[tid];
    float4 bb = reinterpret_cast<const float4*>(b)[tid];
    __half2 h0 = __floats2half2_rn((v.x - mean) * rstd * gg.x + bb.x,
                                   (v.y - mean) * rstd * gg.y + bb.y);
    __half2 h1 = __floats2half2_rn((v.z - mean) * rstd * gg.z + bb.z,
                                   (v.w - mean) * rstd * gg.w + bb.w);
    __half2* op = reinterpret_cast<__half2*>(out + row * C_);
    op[tid * 2]     = h0;
    op[tid * 2 + 1] = h1;
}

// =================== WKV v2: cp.async smem-pipelined recurrence ===================
// 128 blocks x 64 threads; block = (batch b, 64-channel group). 5 stages x 8 timesteps.
// Producers: tid -> (tensor 0..3, 16B segment 0..15); fully coalesced 256B rows.
// Consumer: thread owns channel tid; copies stage to regs, runs serial chain.
#define WKV_TD 8
#define WKV_S  5
// smem per tensor per stage: 8 * 64 * 4 = 2048 B; total 4 * 5 * 2048 = 40960 B (static ok)

__global__ __launch_bounds__(64)
void wkv_pipe(const float* __restrict__ kvr, const float* __restrict__ x,
              const float* __restrict__ tmk, const float* __restrict__ tmv,
              const float* __restrict__ tmr,
              const float* __restrict__ wd, const float* __restrict__ uf,
              float* __restrict__ x1, float* __restrict__ state_out) {
    __shared__ float stg[4 * WKV_S * WKV_TD * 64];
    const uint32_t su = smem_u32(stg);

    const int tid = threadIdx.x;
    const int b = blockIdx.x >> 4;          // 16 channel-groups of 64
    const int cg = (blockIdx.x & 15) * 64;
    const int c = cg + tid;

    // producer role
    const int pten = tid >> 4;              // 0=k,1=v,2=r,3=x
    const int pseg = (tid & 15) * 4;        // float offset within 64-float row
    const float* kbase = kvr + (size_t)b * T_ * C3_ + cg;
    const float* src_base;
    size_t tstride;
    if (pten == 0)      { src_base = kbase;            tstride = C3_; }
    else if (pten == 1) { src_base = kbase + C_;       tstride = C3_; }
    else if (pten == 2) { src_base = kbase + 2 * C_;   tstride = C3_; }
    else                { src_base = x + (size_t)b * T_ * C_ + cg; tstride = C_; }

    // smem addr for (pten, slot, tt): ((pten*WKV_S + slot)*WKV_TD + tt)*256 bytes
    const uint32_t pbase = su + (uint32_t)pten * (WKV_S * WKV_TD * 256) + (uint32_t)pseg * 4;

    const float mk = tmk[c], mv = tmv[c], mr = tmr[c];
    const float w = wd[c], u = uf[c];
    float aa = 0.f, bb = -1e38f;
    float* ob = x1 + (size_t)b * T_ * C_ + c;

    const int nst = T_ / WKV_TD;            // 256

    // prologue: stages 0..S-2
#pragma unroll
    for (int s = 0; s < WKV_S - 1; s++) {
#pragma unroll
        for (int tt = 0; tt < WKV_TD; tt++) {
            cp16(pbase + (uint32_t)(s * WKV_TD + tt) * 256,
                 src_base + (size_t)(s * WKV_TD + tt) * tstride + pseg);
        }
        CP_COMMIT();
    }

    float xp = 0.f;
#pragma unroll 1
    for (int st = 0; st < nst; st++) {
        const int slot = st % WKV_S;
        CP_WAIT3();
        __syncthreads();

        // produce stage st + S - 1 (into slot (st-1)%S, already consumed)
        const int stp = st + WKV_S - 1;
        if (stp < nst) {
            const int ps = stp % WKV_S;
#pragma unroll
            for (int tt = 0; tt < WKV_TD; tt++) {
                cp16(pbase + (uint32_t)(ps * WKV_TD + tt) * 256,
                     src_base + (size_t)(stp * WKV_TD + tt) * tstride + pseg);
            }
        }
        CP_COMMIT();  // unconditional: keeps wait_group accounting uniform

        // copy stage to registers (channel = tid)
        float kr[WKV_TD], vr[WKV_TD], rr[WKV_TD], xr[WKV_TD];
        const float* sk = stg + (0 * WKV_S + slot) * (WKV_TD * 64);
        const float* sv = stg + (1 * WKV_S + slot) * (WKV_TD * 64);
        const float* sr = stg + (2 * WKV_S + slot) * (WKV_TD * 64);
        const float* sx = stg + (3 * WKV_S + slot) * (WKV_TD * 64);
#pragma unroll
        for (int tt = 0; tt < WKV_TD; tt++) {
            kr[tt] = sk[tt * 64 + tid];
            vr[tt] = sv[tt * 64 + tid];
            rr[tt] = sr[tt * 64 + tid];
            xr[tt] = sx[tt * 64 + tid];
        }
        if (st == 0) xp = xr[0];  // x_prev for t=0 is x[t=0]

#pragma unroll
        for (int tt = 0; tt < WKV_TD; tt++) {
            float km = (kr[tt] - xp) * mk + xp;
            float vm = (vr[tt] - xp) * mv + xp;
            float rm = (rr[tt] - xp) * mr + xp;
            float rsg = __fdividef(1.f, 1.f + __expf(-rm));
            float ww = u + km;
            float d1 = bb - ww;
            float e  = __expf(-fabsf(d1));
            float e1 = (d1 >= 0.f) ? 1.f : e;
            float e2 = (d1 >= 0.f) ? e : 1.f;
            float y  = __fdividef(e1 * aa + e2 * vm, e1 + e2 + 1e-8f);
            ob[(size_t)(st * WKV_TD + tt) * C_] = xr[tt] + rsg * y;
            float wwb = w + bb;
            float d2 = wwb - km;
            float ee = __expf(-fabsf(d2));
            float f1 = (d2 >= 0.f) ? 1.f : ee;
            float f2 = (d2 >= 0.f) ? ee : 1.f;
            float p  = fmaxf(wwb, km);
            aa = f1 * aa + f2 * vm;
            bb = p + __logf(f1 + f2 + 1e-8f);
            xp = xr[tt];
        }
    }
    state_out[(size_t)(b * C_ + c) * 2]     = aa;
    state_out[(size_t)(b * C_ + c) * 2 + 1] = bb;
}

// =================== host ===================
extern "C" void kernel_launch(void* const* d_in, const int* in_sizes, int n_in,
                              void* d_out, int out_size) {
    const float* x    = (const float*)d_in[0];
    const float* wdec = (const float*)d_in[1];
    const float* ufst = (const float*)d_in[2];
    const float* W_tm = (const float*)d_in[3];
    const float* g1   = (const float*)d_in[4];
    const float* b1   = (const float*)d_in[5];
    const float* tmk  = (const float*)d_in[6];
    const float* tmv  = (const float*)d_in[7];
    const float* tmr  = (const float*)d_in[8];
    const float* W_cm = (const float*)d_in[9];
    const float* W_cp = (const float*)d_in[10];
    const float* g2   = (const float*)d_in[11];
    const float* b2   = (const float*)d_in[12];
    const float* cmk  = (const float*)d_in[13];
    const float* cmr  = (const float*)d_in[14];
    float* out = (float*)d_out;

    float *x1, *kvr;
    __half *xnh, *hh, *wtm, *wcm, *wcp;
    cudaGetSymbolAddress((void**)&x1,  g_x1);
    cudaGetSymbolAddress((void**)&kvr, g_kvr);
    cudaGetSymbolAddress((void**)&xnh, g_xnh);
    cudaGetSymbolAddress((void**)&hh,  g_hh);
    cudaGetSymbolAddress((void**)&wtm, g_wtm);
    cudaGetSymbolAddress((void**)&wcm, g_wcm);
    cudaGetSymbolAddress((void**)&wcp, g_wcp);

    float* state_out = out + (size_t)BT_ * C_;

    cudaFuncSetAttribute(gemm_f16<0>, cudaFuncAttributeMaxDynamicSharedMemorySize, SMEMB);
    cudaFuncSetAttribute(gemm_f16<1>, cudaFuncAttributeMaxDynamicSharedMemorySize, SMEMB);
    cudaFuncSetAttribute(gemm_f16<2>, cudaFuncAttributeMaxDynamicSharedMemorySize, SMEMB);

    dim3 wcb(32, 8);
    // 0. weight convert + transpose to fp16 [N][K]
    wconv<<<dim3(C3_ / 32, C_ / 32), wcb>>>(W_tm, wtm, C_, C3_);
    wconv<<<dim3(C4_ / 32, C_ / 32), wcb>>>(W_cm, wcm, C_, C4_);
    wconv<<<dim3(C_ / 32, C4_ / 32), wcb>>>(W_cp, wcp, C4_, C_);

    // 1. LayerNorm 1 -> fp16
    ln_kernel_h<<<BT_, 256>>>(x, g1, b1, xnh);
    // 2. kvr = xn1 @ W_tm   (M=16384, N=3072, K=1024), fp32 out
    gemm_f16<0><<<dim3(C3_ / 128, BT_ / 128), 256, SMEMB>>>(
        xnh, wtm, kvr, BT_, C3_, C_, nullptr, nullptr, nullptr);
    // 3. WKV v2: cp.async-pipelined (token-shift mix + recurrence + residual)
    wkv_pipe<<<128, 64>>>(kvr, x, tmk, tmv, tmr, wdec, ufst, x1, state_out);
    // 4. LayerNorm 2 -> fp16
    ln_kernel_h<<<BT_, 256>>>(x1, g2, b2, xnh);
    // 5. h = relu(mix(xn2 @ W_cm))^2 -> fp16   (M=16384, N=4096, K=1024)
    gemm_f16<1><<<dim3(C4_ / 128, BT_ / 128), 256, SMEMB>>>(
        xnh, wcm, hh, BT_, C4_, C_, x1, cmk, nullptr);
    // 6. out = x1 + sigmoid(mix(xn2)) * (h @ W_cp)   (M=16384, N=1024, K=4096)
    gemm_f16<2><<<dim3(C_ / 128, BT_ / 128), 256, SMEMB>>>(
        hh, wcp, out, BT_, C_, C4_, x1, cmr, xnh);
}

// round 14
// speedup vs baseline: 12.5986x; 1.0880x over previous
#include <cuda_runtime.h>
#include <cuda_fp16.h>
#include <cstdint>
#include <cstddef>

// Problem constants
#define B_ 8
#define T_ 2048
#define C_ 1024
#define BT_ (B_ * T_)        // 16384
#define C3_ (3 * C_)         // 3072
#define C4_ (4 * C_)         // 4096

// ---------------- scratch (static device globals; no allocation) ----------------
__device__ float  g_x1[(size_t)BT_ * C_];    // x after time mixing
__device__ float  g_kvr[(size_t)BT_ * C3_];  // raw kvr from GEMM1 (fp32)
__device__ __half g_xnh[(size_t)BT_ * C_];   // LN output (fp16), xn1 then xn2
__device__ __half g_hh[(size_t)BT_ * C4_];   // channel-mix hidden (fp16, post relu^2)
__device__ __half g_wtm[(size_t)C3_ * C_];   // W_tm^T fp16  [3C][C]
__device__ __half g_wcm[(size_t)C4_ * C_];   // W_cm^T fp16  [4C][C]
__device__ __half g_wcp[(size_t)C_ * C4_];   // W_cp^T fp16  [C][4C]

// =================== small helpers ===================
__device__ __forceinline__ uint32_t smem_u32(const void* p) {
    uint32_t a;
    asm("{ .reg .u64 t; cvta.to.shared.u64 t, %1; cvt.u32.u64 %0, t; }" : "=r"(a) : "l"(p));
    return a;
}
__device__ __forceinline__ void cp16(uint32_t s, const void* g) {
    asm volatile("cp.async.cg.shared.global [%0], [%1], 16;" :: "r"(s), "l"(g));
}
#define CP_COMMIT() asm volatile("cp.async.commit_group;" ::: "memory")
#define CP_WAIT1()  asm volatile("cp.async.wait_group 1;" ::: "memory")
#define CP_WAIT3()  asm volatile("cp.async.wait_group 3;" ::: "memory")

__device__ __forceinline__ void ldsm4(uint32_t* r, uint32_t addr) {
    asm volatile("ldmatrix.sync.aligned.m8n8.x4.shared.b16 {%0,%1,%2,%3}, [%4];"
                 : "=r"(r[0]), "=r"(r[1]), "=r"(r[2]), "=r"(r[3]) : "r"(addr));
}
__device__ __forceinline__ void mma_f16(float* c, const uint32_t* a, const uint32_t* b) {
    asm volatile(
        "mma.sync.aligned.m16n8k16.row.col.f32.f16.f16.f32 "
        "{%0,%1,%2,%3}, {%4,%5,%6,%7}, {%8,%9}, {%0,%1,%2,%3};\n"
        : "+f"(c[0]), "+f"(c[1]), "+f"(c[2]), "+f"(c[3])
        : "r"(a[0]), "r"(a[1]), "r"(a[2]), "r"(a[3]), "r"(b[0]), "r"(b[1]));
}
__device__ __forceinline__ float sigmoidf_(float z) {
    return 1.0f / (1.0f + __expf(-z));
}

// =================== fp16 tensor GEMM: 3-stage cp.async, 2 CTAs/SM ====================
// C[M,N] = A[M,K] @ B[K,N]; A fp16 [M][K] row-major, Bt fp16 [N][K] (pre-transposed).
// CTA tile 128x128, BK=32, 256 threads (8 warps = 4x2, warp tile 32x64).
#define ROWB   80
#define TILEB  (128 * ROWB)      // 10240
#define STAGEB (2 * TILEB)       // 20480
#define SMEMB  (3 * STAGEB)      // 61440 -> 2 CTAs/SM

// EPI: 0 = plain fp32 store (kvr); 1 = channel-mix relu^2 -> fp16; 2 = final residual fp32
template <int EPI>
__device__ __forceinline__ void epi2(void* __restrict__ Cout, int N, int row, int col,
                                     float v0, float v1,
                                     const float* __restrict__ x1p,
                                     const float* __restrict__ gate,
                                     const __half* __restrict__ xn2) {
    if (EPI == 0) {
        *(float2*)&((float*)Cout)[(size_t)row * N + col] = make_float2(v0, v1);
    } else if (EPI == 1) {
        int t = row & (T_ - 1);
        int rp = row - t + ((t > 0) ? t - 1 : T_ - 1);
        int c0 = col & (C_ - 1), c1 = (col + 1) & (C_ - 1);
        float xp0 = x1p[(size_t)rp * C_ + c0];
        float xp1 = x1p[(size_t)rp * C_ + c1];
        float k0 = fmaxf((v0 - xp0) * gate[c0] + xp0, 0.f);
        float k1 = fmaxf((v1 - xp1) * gate[c1] + xp1, 0.f);
        *(__half2*)&((__half*)Cout)[(size_t)row * N + col] = __floats2half2_rn(k0 * k0, k1 * k1);
    } else {
        int t = row & (T_ - 1);
        int rp = row - t + ((t > 0) ? t - 1 : T_ - 1);
        float xp0 = x1p[(size_t)rp * C_ + col];
        float xp1 = x1p[(size_t)rp * C_ + col + 1];
        size_t o = (size_t)row * C_ + col;
        float r0 = sigmoidf_((__half2float(xn2[o])     - xp0) * gate[col]     + xp0);
        float r1 = sigmoidf_((__half2float(xn2[o + 1]) - xp1) * gate[col + 1] + xp1);
        *(float2*)&((float*)Cout)[o] = make_float2(x1p[o] + r0 * v0, x1p[o + 1] + r1 * v1);
    }
}

template <int EPI>
__global__ __launch_bounds__(256, 2)
void gemm_f16(const __half* __restrict__ A, const __half* __restrict__ Bt,
              void* __restrict__ Cout, int M, int N, int K,
              const float* __restrict__ e_x1, const float* __restrict__ e_gate,
              const __half* __restrict__ e_xn2) {
    extern __shared__ char dsm[];
    const uint32_t su = smem_u32(dsm);

    const int tid = threadIdx.x;
    const int lane = tid & 31;
    const int wid = tid >> 5;
    const int wm = (wid & 3) * 32;
    const int wn = (wid >> 2) * 64;
    const int g = lane >> 2;
    const int tig = lane & 3;

    const int m0 = blockIdx.y * 128;
    const int n0 = blockIdx.x * 128;

    const int prow = tid >> 2;
    const int pseg = tid & 3;
    const __half* Ap0 = A + (size_t)(m0 + prow) * K + pseg * 8;
    const __half* Ap1 = A + (size_t)(m0 + prow + 64) * K + pseg * 8;
    const __half* Bp0 = Bt + (size_t)(n0 + prow) * K + pseg * 8;
    const __half* Bp1 = Bt + (size_t)(n0 + prow + 64) * K + pseg * 8;
    const uint32_t soA0 = (uint32_t)(prow * ROWB + pseg * 16);
    const uint32_t soA1 = (uint32_t)((prow + 64) * ROWB + pseg * 16);
    const uint32_t soB0 = TILEB + soA0;
    const uint32_t soB1 = TILEB + soA1;

    const int ntiles = K >> 5;

    // prologue: stages 0, 1
#pragma unroll
    for (int s = 0; s < 2; s++) {
        uint32_t sb0 = su + s * STAGEB;
        size_t koff = (size_t)s * 32;
        cp16(sb0 + soA0, Ap0 + koff);
        cp16(sb0 + soA1, Ap1 + koff);
        cp16(sb0 + soB0, Bp0 + koff);
        cp16(sb0 + soB1, Bp1 + koff);
        CP_COMMIT();
    }

    float acc[2][8][4];
#pragma unroll
    for (int i = 0; i < 2; i++)
#pragma unroll
        for (int j = 0; j < 8; j++)
#pragma unroll
            for (int v = 0; v < 4; v++) acc[i][j][v] = 0.f;

    const uint32_t aro = (uint32_t)(lane & 15) * ROWB + (uint32_t)(lane >> 4) * 16;
    const uint32_t bro = (uint32_t)((lane & 7) + ((lane >> 4) << 3)) * ROWB
                       + (uint32_t)((lane >> 3) & 1) * 16;

    int cur = 0, nxt = 2;   // slot of stage kt, slot of stage kt+2
    for (int kt = 0; kt < ntiles; kt++) {
        CP_WAIT1();
        __syncthreads();

        if (kt + 2 < ntiles) {
            uint32_t sb0 = su + nxt * STAGEB;
            size_t koff = (size_t)(kt + 2) * 32;
            cp16(sb0 + soA0, Ap0 + koff);
            cp16(sb0 + soA1, Ap1 + koff);
            cp16(sb0 + soB0, Bp0 + koff);
            cp16(sb0 + soB1, Bp1 + koff);
        }
        CP_COMMIT();  // unconditional: uniform group accounting

        const uint32_t st = su + cur * STAGEB;
#pragma unroll
        for (int ks = 0; ks < 2; ks++) {
            uint32_t a[2][4];
#pragma unroll
            for (int i = 0; i < 2; i++)
                ldsm4(a[i], st + (uint32_t)(wm + i * 16) * ROWB + ks * 32 + aro);
#pragma unroll
            for (int jj = 0; jj < 4; jj++) {
                uint32_t bfr[4];
                ldsm4(bfr, st + TILEB + (uint32_t)(wn + jj * 16) * ROWB + ks * 32 + bro);
#pragma unroll
                for (int i = 0; i < 2; i++) {
                    mma_f16(acc[i][2 * jj],     a[i], bfr + 0);
                    mma_f16(acc[i][2 * jj + 1], a[i], bfr + 2);
                }
            }
        }
        __syncthreads();
        cur = (cur == 2) ? 0 : cur + 1;
        nxt = (nxt == 2) ? 0 : nxt + 1;
    }

#pragma unroll
    for (int i = 0; i < 2; i++) {
        const int row = m0 + wm + i * 16 + g;
#pragma unroll
        for (int j = 0; j < 8; j++) {
            const int col = n0 + wn + j * 8 + 2 * tig;
            epi2<EPI>(Cout, N, row,     col, acc[i][j][0], acc[i][j][1], e_x1, e_gate, e_xn2);
            epi2<EPI>(Cout, N, row + 8, col, acc[i][j][2], acc[i][j][3], e_x1, e_gate, e_xn2);
        }
    }
}

// =================== weight convert + transpose: fp32 [K][N] -> fp16 [N][K] ===========
__global__ void wconv(const float* __restrict__ in, __half* __restrict__ out, int K, int N) {
    __shared__ float t[32][33];
    int n0 = blockIdx.x * 32, k0 = blockIdx.y * 32;
    int tx = threadIdx.x, ty = threadIdx.y;  // 32x8
#pragma unroll
    for (int q = 0; q < 4; q++)
        t[ty + q * 8][tx] = in[(size_t)(k0 + ty + q * 8) * N + n0 + tx];
    __syncthreads();
#pragma unroll
    for (int q = 0; q < 4; q++)
        out[(size_t)(n0 + ty + q * 8) * K + k0 + tx] = __float2half_rn(t[tx][ty + q * 8]);
}

// =================== LayerNorm -> fp16 ===================
__global__ void ln_kernel_h(const float* __restrict__ x,
                            const float* __restrict__ g,
                            const float* __restrict__ b,
                            __half* __restrict__ out) {
    size_t row = blockIdx.x;
    int tid = threadIdx.x;
    const float4* xr = reinterpret_cast<const float4*>(x + row * C_);
    float4 v = xr[tid];
    float s = v.x + v.y + v.z + v.w;
    float s2 = v.x * v.x + v.y * v.y + v.z * v.z + v.w * v.w;

    __shared__ float sa[8], sb[8];
    for (int o = 16; o > 0; o >>= 1) {
        s  += __shfl_down_sync(0xffffffffu, s, o);
        s2 += __shfl_down_sync(0xffffffffu, s2, o);
    }
    int w = tid >> 5, l = tid & 31;
    if (l == 0) { sa[w] = s; sb[w] = s2; }
    __syncthreads();
    if (w == 0) {
        s  = (l < 8) ? sa[l] : 0.f;
        s2 = (l < 8) ? sb[l] : 0.f;
        for (int o = 4; o > 0; o >>= 1) {
            s  += __shfl_down_sync(0xffffffffu, s, o);
            s2 += __shfl_down_sync(0xffffffffu, s2, o);
        }
        if (l == 0) { sa[0] = s; sb[0] = s2; }
    }
    __syncthreads();
    float mean = sa[0] * (1.0f / C_);
    float var = sb[0] * (1.0f / C_) - mean * mean;
    float rstd = rsqrtf(var + 1e-5f);

    float4 gg = reinterpret_cast<const float4*>(g)[tid];
    float4 bb = reinterpret_cast<const float4*>(b)[tid];
    __half2 h0 = __floats2half2_rn((v.x - mean) * rstd * gg.x + bb.x,
                                   (v.y - mean) * rstd * gg.y + bb.y);
    __half2 h1 = __floats2half2_rn((v.z - mean) * rstd * gg.z + bb.z,
                                   (v.w - mean) * rstd * gg.w + bb.w);
    __half2* op = reinterpret_cast<__half2*>(out + row * C_);
    op[tid * 2]     = h0;
    op[tid * 2 + 1] = h1;
}

// =================== WKV v3: cp.async pipeline + exp-domain recurrence ===================
// State carried as (P, S, aa) with bb = P + log S; log folded once per 8-step block.
// e1/e2 values match the reference's exp(bb-p)/exp(k-p) modulo fp rounding.
#define WKV_TD 8
#define WKV_S  5

__global__ __launch_bounds__(64)
void wkv_pipe(const float* __restrict__ kvr, const float* __restrict__ x,
              const float* __restrict__ tmk, const float* __restrict__ tmv,
              const float* __restrict__ tmr,
              const float* __restrict__ wd, const float* __restrict__ uf,
              float* __restrict__ x1, float* __restrict__ state_out) {
    __shared__ float stg[4 * WKV_S * WKV_TD * 64];
    const uint32_t su = smem_u32(stg);

    const int tid = threadIdx.x;
    const int b = blockIdx.x >> 4;
    const int cg = (blockIdx.x & 15) * 64;
    const int c = cg + tid;

    const int pten = tid >> 4;
    const int pseg = (tid & 15) * 4;
    const float* kbase = kvr + (size_t)b * T_ * C3_ + cg;
    const float* src_base;
    size_t tstride;
    if (pten == 0)      { src_base = kbase;            tstride = C3_; }
    else if (pten == 1) { src_base = kbase + C_;       tstride = C3_; }
    else if (pten == 2) { src_base = kbase + 2 * C_;   tstride = C3_; }
    else                { src_base = x + (size_t)b * T_ * C_ + cg; tstride = C_; }

    const uint32_t pbase = su + (uint32_t)pten * (WKV_S * WKV_TD * 256) + (uint32_t)pseg * 4;

    const float mk = tmk[c], mv = tmv[c], mr = tmr[c];
    const float w = wd[c], u = uf[c];
    float aa = 0.f;
    float P = -1e38f, S = 1.0f;      // bb = P + log(S)
    float* ob = x1 + (size_t)b * T_ * C_ + c;

    const int nst = T_ / WKV_TD;

#pragma unroll
    for (int s = 0; s < WKV_S - 1; s++) {
#pragma unroll
        for (int tt = 0; tt < WKV_TD; tt++) {
            cp16(pbase + (uint32_t)(s * WKV_TD + tt) * 256,
                 src_base + (size_t)(s * WKV_TD + tt) * tstride + pseg);
        }
        CP_COMMIT();
    }

    float xp = 0.f;
#pragma unroll 1
    for (int st = 0; st < nst; st++) {
        const int slot = st % WKV_S;
        CP_WAIT3();
        __syncthreads();

        const int stp = st + WKV_S - 1;
        if (stp < nst) {
            const int ps = stp % WKV_S;
#pragma unroll
            for (int tt = 0; tt < WKV_TD; tt++) {
                cp16(pbase + (uint32_t)(ps * WKV_TD + tt) * 256,
                     src_base + (size_t)(stp * WKV_TD + tt) * tstride + pseg);
            }
        }
        CP_COMMIT();

        float kr[WKV_TD], vr[WKV_TD], rr[WKV_TD], xr[WKV_TD];
        const float* sk = stg + (0 * WKV_S + slot) * (WKV_TD * 64);
        const float* sv = stg + (1 * WKV_S + slot) * (WKV_TD * 64);
        const float* sr = stg + (2 * WKV_S + slot) * (WKV_TD * 64);
        const float* sx = stg + (3 * WKV_S + slot) * (WKV_TD * 64);
#pragma unroll
        for (int tt = 0; tt < WKV_TD; tt++) {
            kr[tt] = sk[tt * 64 + tid];
            vr[tt] = sv[tt * 64 + tid];
            rr[tt] = sr[tt * 64 + tid];
            xr[tt] = sx[tt * 64 + tid];
        }
        if (st == 0) xp = xr[0];

#pragma unroll
        for (int tt = 0; tt < WKV_TD; tt++) {
            float km = (kr[tt] - xp) * mk + xp;
            float vm = (vr[tt] - xp) * mv + xp;
            float rm = (rr[tt] - xp) * mr + xp;
            float rsg = __fdividef(1.f, 1.f + __expf(-rm));
            float rcpS = __fdividef(1.f, S);
            // ---- y: q = max(bb, u+km); e1 = exp(bb-q), e2 = exp(u+km-q) ----
            float a2 = u + km - P;
            float g2  = __expf(a2);
            float g2i = __expf(-a2);
            bool  c2 = (S >= g2);                 // bb >= u+km
            float e1 = c2 ? 1.f : S * g2i;
            float e2 = c2 ? g2 * rcpS : 1.f;
            float y  = __fdividef(e1 * aa + e2 * vm, e1 + e2 + 1e-8f);
            ob[(size_t)(st * WKV_TD + tt) * C_] = xr[tt] + rsg * y;
            // ---- state: p = max(w+bb, km); f1 = exp(w+bb-p), f2 = exp(km-p) ----
            float a1 = km - w - P;
            float g1  = __expf(a1);
            float g1i = __expf(-a1);
            bool  c1 = (S >= g1);                 // w+bb >= km
            float f2  = c1 ? g1 * rcpS : 1.f;
            float f1s = c1 ? 1.f : S * g1i;
            aa = f1s * aa + f2 * vm;
            S  = c1 ? (S + g1) : (S * g1i + 1.f);
            P  = c1 ? (w + P) : km;
            xp = xr[tt];
        }
        // fold normalization once per block of 8 steps
        P += __logf(S);
        S = 1.0f;
    }
    state_out[(size_t)(b * C_ + c) * 2]     = aa;
    state_out[(size_t)(b * C_ + c) * 2 + 1] = P;   // S == 1 after fold
}

// =================== host ===================
extern "C" void kernel_launch(void* const* d_in, const int* in_sizes, int n_in,
                              void* d_out, int out_size) {
    const float* x    = (const float*)d_in[0];
    const float* wdec = (const float*)d_in[1];
    const float* ufst = (const float*)d_in[2];
    const float* W_tm = (const float*)d_in[3];
    const float* g1   = (const float*)d_in[4];
    const float* b1   = (const float*)d_in[5];
    const float* tmk  = (const float*)d_in[6];
    const float* tmv  = (const float*)d_in[7];
    const float* tmr  = (const float*)d_in[8];
    const float* W_cm = (const float*)d_in[9];
    const float* W_cp = (const float*)d_in[10];
    const float* g2   = (const float*)d_in[11];
    const float* b2   = (const float*)d_in[12];
    const float* cmk  = (const float*)d_in[13];
    const float* cmr  = (const float*)d_in[14];
    float* out = (float*)d_out;

    float *x1, *kvr;
    __half *xnh, *hh, *wtm, *wcm, *wcp;
    cudaGetSymbolAddress((void**)&x1,  g_x1);
    cudaGetSymbolAddress((void**)&kvr, g_kvr);
    cudaGetSymbolAddress((void**)&xnh, g_xnh);
    cudaGetSymbolAddress((void**)&hh,  g_hh);
    cudaGetSymbolAddress((void**)&wtm, g_wtm);
    cudaGetSymbolAddress((void**)&wcm, g_wcm);
    cudaGetSymbolAddress((void**)&wcp, g_wcp);

    float* state_out = out + (size_t)BT_ * C_;

    cudaFuncSetAttribute(gemm_f16<0>, cudaFuncAttributeMaxDynamicSharedMemorySize, SMEMB);
    cudaFuncSetAttribute(gemm_f16<1>, cudaFuncAttributeMaxDynamicSharedMemorySize, SMEMB);
    cudaFuncSetAttribute(gemm_f16<2>, cudaFuncAttributeMaxDynamicSharedMemorySize, SMEMB);

    dim3 wcb(32, 8);
    // 0. weight convert + transpose to fp16 [N][K]
    wconv<<<dim3(C3_ / 32, C_ / 32), wcb>>>(W_tm, wtm, C_, C3_);
    wconv<<<dim3(C4_ / 32, C_ / 32), wcb>>>(W_cm, wcm, C_, C4_);
    wconv<<<dim3(C_ / 32, C4_ / 32), wcb>>>(W_cp, wcp, C4_, C_);

    // 1. LayerNorm 1 -> fp16
    ln_kernel_h<<<BT_, 256>>>(x, g1, b1, xnh);
    // 2. kvr = xn1 @ W_tm   (M=16384, N=3072, K=1024), fp32 out
    gemm_f16<0><<<dim3(C3_ / 128, BT_ / 128), 256, SMEMB>>>(
        xnh, wtm, kvr, BT_, C3_, C_, nullptr, nullptr, nullptr);
    // 3. WKV v3 (cp.async pipeline + exp-domain recurrence) -> x1, state
    wkv_pipe<<<128, 64>>>(kvr, x, tmk, tmv, tmr, wdec, ufst, x1, state_out);
    // 4. LayerNorm 2 -> fp16
    ln_kernel_h<<<BT_, 256>>>(x1, g2, b2, xnh);
    // 5. h = relu(mix(xn2 @ W_cm))^2 -> fp16   (M=16384, N=4096, K=1024)
    gemm_f16<1><<<dim3(C4_ / 128, BT_ / 128), 256, SMEMB>>>(
        xnh, wcm, hh, BT_, C4_, C_, x1, cmk, nullptr);
    // 6. out = x1 + sigmoid(mix(xn2)) * (h @ W_cp)   (M=16384, N=1024, K=4096)
    gemm_f16<2><<<dim3(C_ / 128, BT_ / 128), 256, SMEMB>>>(
        hh, wcp, out, BT_, C_, C4_, x1, cmr, xnh);
}